// round 11
// baseline (speedup 1.0000x reference)
#include <cuda_runtime.h>
#include <cuda_fp16.h>
#include <math.h>
#include <stdint.h>

#define BB 2
#define SS 2048
#define DD 1024
#define HH 16
#define GM (BB*SS)   /* 4096 */
#define GN DD
#define GK DD

// ---------------- scratch (allocation-free) ----------------
__device__ __half g_Xh[GM*DD],  g_Xl[GM*DD];
__device__ __half g_Qh[GM*DD],  g_Ql[GM*DD];
__device__ __half g_Kh[GM*DD];
__device__ __half g_Vh[GM*DD];
__device__ __half g_AOh[GM*DD], g_AOl[GM*DD];
__device__ __half g_LoSink[GM*DD];   // discard target for unused lo outputs
__device__ __half g_Wqh[DD*DD];
__device__ __half g_Wkh[DD*DD];
__device__ __half g_Wvh[DD*DD];
__device__ __half g_Woh[DD*DD];

// ---------------- helpers ----------------
__device__ __forceinline__ uint32_t smem_u32(const void* p) {
    return (uint32_t)__cvta_generic_to_shared(p);
}
__device__ __forceinline__ void cp_async16(uint32_t dst, const void* src) {
    asm volatile("cp.async.cg.shared.global [%0], [%1], 16;" :: "r"(dst), "l"(src) : "memory");
}
__device__ __forceinline__ void cp_commit() {
    asm volatile("cp.async.commit_group;" ::: "memory");
}
template<int N>
__device__ __forceinline__ void cp_wait() {
    asm volatile("cp.async.wait_group %0;" :: "n"(N) : "memory");
}
__device__ __forceinline__ void ldm_x4(uint32_t* r, uint32_t addr) {
    asm volatile("ldmatrix.sync.aligned.m8n8.x4.shared.b16 {%0,%1,%2,%3}, [%4];"
                 : "=r"(r[0]), "=r"(r[1]), "=r"(r[2]), "=r"(r[3]) : "r"(addr));
}
__device__ __forceinline__ void ldm_x4_t(uint32_t* r, uint32_t addr) {
    asm volatile("ldmatrix.sync.aligned.m8n8.x4.trans.shared.b16 {%0,%1,%2,%3}, [%4];"
                 : "=r"(r[0]), "=r"(r[1]), "=r"(r[2]), "=r"(r[3]) : "r"(addr));
}
__device__ __forceinline__ void mma_f32acc(float* c, const uint32_t* a, const uint32_t* b) {
    asm volatile("mma.sync.aligned.m16n8k16.row.col.f32.f16.f16.f32 "
                 "{%0,%1,%2,%3}, {%4,%5,%6,%7}, {%8,%9}, {%0,%1,%2,%3};"
                 : "+f"(c[0]), "+f"(c[1]), "+f"(c[2]), "+f"(c[3])
                 : "r"(a[0]), "r"(a[1]), "r"(a[2]), "r"(a[3]), "r"(b[0]), "r"(b[1]));
}
__device__ __forceinline__ uint32_t packh2(float a, float b) {
    __half2 h = __floats2half2_rn(a, b);
    return *(uint32_t*)&h;
}
__device__ __forceinline__ float2 unpackh2(uint32_t r) {
    __half2 h = *(__half2*)&r;
    return __half22float2(h);
}
__device__ __forceinline__ float warp_rmax(float x) {
    x = fmaxf(x, __shfl_xor_sync(0xffffffffu, x, 1));
    x = fmaxf(x, __shfl_xor_sync(0xffffffffu, x, 2));
    return x;
}
__device__ __forceinline__ float warp_rsum(float x) {
    x += __shfl_xor_sync(0xffffffffu, x, 1);
    x += __shfl_xor_sync(0xffffffffu, x, 2);
    return x;
}

// ---------------- split fp32 -> f16 hi + f16 lo (unscaled) ----------------
__global__ void split_f16(const float* __restrict__ in, __half* __restrict__ hi,
                          __half* __restrict__ lo, int n4)
{
    int i = blockIdx.x*blockDim.x + threadIdx.x;
    int stride = gridDim.x*blockDim.x;
    const float4* in4 = (const float4*)in;
    uint32_t* h2 = (uint32_t*)hi;
    uint32_t* l2 = (uint32_t*)lo;
    for (; i < n4; i += stride) {
        float4 v = in4[i];
        uint32_t h01 = packh2(v.x, v.y), h23 = packh2(v.z, v.w);
        float2 f01 = unpackh2(h01), f23 = unpackh2(h23);
        uint32_t l01 = packh2(v.x - f01.x, v.y - f01.y);
        uint32_t l23 = packh2(v.z - f23.x, v.w - f23.y);
        h2[i*2] = h01; h2[i*2+1] = h23;
        l2[i*2] = l01; l2[i*2+1] = l23;
    }
}
__global__ void conv_f16(const float* __restrict__ in, __half* __restrict__ hi, int n4)
{
    int i = blockIdx.x*blockDim.x + threadIdx.x;
    int stride = gridDim.x*blockDim.x;
    const float4* in4 = (const float4*)in;
    uint32_t* h2 = (uint32_t*)hi;
    for (; i < n4; i += stride) {
        float4 v = in4[i];
        h2[i*2]   = packh2(v.x, v.y);
        h2[i*2+1] = packh2(v.z, v.w);
    }
}

// ---------------- 2-pass f16 GEMM: C = alpha * ((Ah+Al) @ Bh^T) ----------------
#define KCH 64
#define NCH (GK/KCH)
#define SRE 72
#define SRB (SRE*2)
#define TILE_B (128*SRB)
#define STAGE_B (3*TILE_B)          /* Ah, Al, Bh = 55296 */
#define GEMM_SMEM (3*STAGE_B)       /* 165888 */

template<bool SPLIT>
__global__ __launch_bounds__(256, 1)
void gemm_f16x2(const __half* __restrict__ Ah, const __half* __restrict__ Al,
                const __half* __restrict__ Bh,
                float* __restrict__ Cf, __half* __restrict__ Chi,
                __half* __restrict__ Clo, float alpha)
{
    extern __shared__ char smem[];
    const uint32_t sb = smem_u32(smem);
    const int tid  = threadIdx.x;
    const int lane = tid & 31;
    const int warp = tid >> 5;
    const int wm   = warp & 3;
    const int wn   = warp >> 2;
    const int cRow = blockIdx.y << 7;
    const int cCol = blockIdx.x << 7;

    const __half* gsrc[3];
    gsrc[0] = Ah + (size_t)cRow*GK;
    gsrc[1] = Al + (size_t)cRow*GK;
    gsrc[2] = Bh + (size_t)cCol*GK;

    const int ldRow = tid >> 3;
    const int ldCol = tid & 7;

    const uint32_t aOff = (uint32_t)((lane & 15)*SRB + (lane >> 4)*16 + wm*32*SRB);
    const uint32_t bOff = (uint32_t)(((lane & 7) + ((lane >> 4) << 3))*SRB
                                     + ((lane >> 3) & 1)*16 + wn*64*SRB);

    float acc[2][8][4];
#pragma unroll
    for (int mt = 0; mt < 2; mt++)
#pragma unroll
        for (int nt = 0; nt < 8; nt++)
#pragma unroll
            for (int q = 0; q < 4; q++) acc[mt][nt][q] = 0.f;

    auto issue_chunk = [&](int j, int s) {
        const uint32_t st = sb + (uint32_t)s*STAGE_B;
        const int k0 = j*KCH;
#pragma unroll
        for (int t = 0; t < 3; t++)
#pragma unroll
            for (int i = 0; i < 4; i++) {
                int row = ldRow + i*32;
                cp_async16(st + t*TILE_B + row*SRB + ldCol*16,
                           gsrc[t] + (size_t)row*GK + k0 + ldCol*8);
            }
        cp_commit();
    };

    issue_chunk(0, 0);
    issue_chunk(1, 1);

    for (int j = 0; j < NCH; j++) {
        if (j + 2 < NCH) issue_chunk(j + 2, (j + 2) % 3);
        if (j + 2 < NCH)      cp_wait<2>();
        else if (j + 1 < NCH) cp_wait<1>();
        else                  cp_wait<0>();
        __syncthreads();

        const uint32_t stg = sb + (uint32_t)(j % 3)*STAGE_B;
        const uint32_t aBH = stg + aOff;
        const uint32_t aBL = stg + TILE_B + aOff;
        const uint32_t bBH = stg + 2*TILE_B + bOff;
#pragma unroll
        for (int k16 = 0; k16 < 4; k16++) {
            uint32_t ah2[2][4], al2[2][4], bh2[4][4];
            ldm_x4(ah2[0], aBH + k16*32);
            ldm_x4(ah2[1], aBH + k16*32 + 16*SRB);
            ldm_x4(al2[0], aBL + k16*32);
            ldm_x4(al2[1], aBL + k16*32 + 16*SRB);
#pragma unroll
            for (int ng = 0; ng < 4; ng++)
                ldm_x4(bh2[ng], bBH + k16*32 + ng*16*SRB);
#pragma unroll
            for (int mt = 0; mt < 2; mt++)
#pragma unroll
                for (int ng = 0; ng < 4; ng++) {
                    mma_f32acc(acc[mt][2*ng+0], ah2[mt], &bh2[ng][0]);
                    mma_f32acc(acc[mt][2*ng+1], ah2[mt], &bh2[ng][2]);
                    mma_f32acc(acc[mt][2*ng+0], al2[mt], &bh2[ng][0]);
                    mma_f32acc(acc[mt][2*ng+1], al2[mt], &bh2[ng][2]);
                }
        }
        __syncthreads();
    }

    const int gid = lane >> 2, tig = lane & 3;
#pragma unroll
    for (int mt = 0; mt < 2; mt++) {
        const int m0 = cRow + wm*32 + mt*16 + gid;
#pragma unroll
        for (int nt = 0; nt < 8; nt++) {
            const int n = cCol + wn*64 + nt*8 + tig*2;
            float v0 = acc[mt][nt][0]*alpha, v1 = acc[mt][nt][1]*alpha;
            float v2 = acc[mt][nt][2]*alpha, v3 = acc[mt][nt][3]*alpha;
            if (SPLIT) {
                uint32_t h01 = packh2(v0, v1), h23 = packh2(v2, v3);
                float2 f01 = unpackh2(h01), f23 = unpackh2(h23);
                uint32_t l01 = packh2(v0 - f01.x, v1 - f01.y);
                uint32_t l23 = packh2(v2 - f23.x, v3 - f23.y);
                *(uint32_t*)(Chi + (size_t)m0*GN + n)     = h01;
                *(uint32_t*)(Clo + (size_t)m0*GN + n)     = l01;
                *(uint32_t*)(Chi + (size_t)(m0+8)*GN + n) = h23;
                *(uint32_t*)(Clo + (size_t)(m0+8)*GN + n) = l23;
            } else {
                float2 a0 = {v0, v1}, a1 = {v2, v3};
                *(float2*)(Cf + (size_t)m0*GN + n)     = a0;
                *(float2*)(Cf + (size_t)(m0+8)*GN + n) = a1;
            }
        }
    }
}

// ---------------------------------------------------------------------------
// Flash attention, causal, 2-pass f16: S=(Qh+Ql)Kh, O=(Ph+Pl)Vh. 3-stage KV.
// ---------------------------------------------------------------------------
#define FQSTR 72
#define FTILE (64*FQSTR*2)
#define FSTAGE (2*FTILE)                         /* Kh,Vh = 18432 */
#define FLASH_SMEM (2*128*FQSTR*2 + 3*FSTAGE)    /* 92160 */

__global__ __launch_bounds__(256, 1)
void flash_mma(const __half* __restrict__ Qh_, const __half* __restrict__ Ql_,
               const __half* __restrict__ Kh_, const __half* __restrict__ Vh_,
               __half* __restrict__ AOh, __half* __restrict__ AOl)
{
    extern __shared__ char smc[];
    const int qt  = (int)gridDim.x - 1 - (int)blockIdx.x;
    const int h   = blockIdx.y, b = blockIdx.z;
    const int tid = threadIdx.x;
    const int lane = tid & 31, w = tid >> 5;
    const int qbase = qt*128;
    const int ktmax = 2*qt + 1;

    const uint32_t sb  = smem_u32(smc);
    const uint32_t uQh = sb;
    const uint32_t uQl = sb + 128*FQSTR*2;
    const uint32_t uKV = sb + 2*128*FQSTR*2;

    const __half* qsrc[2]  = {Qh_, Ql_};
    const __half* kvsrc[2] = {Kh_, Vh_};
    const size_t hofs = (size_t)h*64;

    auto load_kv = [&](int kt, int s) {
#pragma unroll
        for (int i = 0; i < 4; i++) {
            int id = tid + i*256;
            int a = id >> 9, r = (id >> 3) & 63, c = id & 7;
            const __half* g = kvsrc[a] + (size_t)(b*SS + kt*64 + r)*DD + hofs + c*8;
            cp_async16(uKV + s*FSTAGE + a*FTILE + (uint32_t)(r*FQSTR + c*8)*2, g);
        }
    };

#pragma unroll
    for (int i = 0; i < 8; i++) {
        int id = tid + i*256;
        int a = id >> 10, r = (id >> 3) & 127, c = id & 7;
        const __half* g = qsrc[a] + (size_t)(b*SS + qbase + r)*DD + hofs + c*8;
        cp_async16((a ? uQl : uQh) + (uint32_t)(r*FQSTR + c*8)*2, g);
    }
    load_kv(0, 0);
    cp_commit();
    load_kv(1, 1);
    cp_commit();

    const int gid = lane >> 2, tig = lane & 3;
    const int qrow_off = ((lane>>3)&1)*8 + (lane&7);
    const int qd_off   = (lane>>4)*8;
    const int krow_off = (lane>>4)*8 + (lane&7);
    const int kd_off   = ((lane>>3)&1)*8;
    const int vrow_off = ((lane>>3)&1)*8 + (lane&7);
    const int vd_off   = (lane>>4)*8;

    uint32_t qh[4][4], ql[4][4];

    float m0 = -INFINITY, m1 = -INFINITY, l0 = 0.f, l1 = 0.f;
    float oacc[8][4];
#pragma unroll
    for (int nt = 0; nt < 8; nt++)
#pragma unroll
        for (int q = 0; q < 4; q++) oacc[nt][q] = 0.f;

    const int row0 = qbase + 16*w + gid;
    const int row1 = row0 + 8;

    for (int kt = 0; kt <= ktmax; kt++) {
        if (kt + 2 <= ktmax) { load_kv(kt + 2, (kt + 2) % 3); cp_commit(); }
        if (kt + 2 <= ktmax)      cp_wait<2>();
        else if (kt + 1 <= ktmax) cp_wait<1>();
        else                      cp_wait<0>();
        __syncthreads();

        if (kt == 0) {
            uint32_t ah = uQh + (uint32_t)((16*w + qrow_off)*FQSTR + qd_off)*2;
            uint32_t al = uQl + (uint32_t)((16*w + qrow_off)*FQSTR + qd_off)*2;
#pragma unroll
            for (int kk = 0; kk < 4; kk++) {
                ldm_x4(qh[kk], ah + kk*32);
                ldm_x4(ql[kk], al + kk*32);
            }
        }

        const uint32_t st = uKV + (uint32_t)(kt % 3)*FSTAGE;
        const bool active = (kt*64 <= qbase + 16*w + 15);
        if (active) {
            float sacc[8][4];
#pragma unroll
            for (int nt = 0; nt < 8; nt++)
#pragma unroll
                for (int q = 0; q < 4; q++) sacc[nt][q] = 0.f;

            // ---- S = (Qh + Ql) * Kh ----
#pragma unroll
            for (int kk = 0; kk < 4; kk++) {
                const uint32_t kb0 = st + (uint32_t)(krow_off*FQSTR + kd_off + 16*kk)*2;
                uint32_t kb[8][2];
#pragma unroll
                for (int p = 0; p < 4; p++) {
                    uint32_t r[4];
                    ldm_x4(r, kb0 + (uint32_t)(16*p*FQSTR)*2);
                    kb[2*p][0] = r[0]; kb[2*p][1] = r[1];
                    kb[2*p+1][0] = r[2]; kb[2*p+1][1] = r[3];
                }
#pragma unroll
                for (int nt = 0; nt < 8; nt++) {
                    mma_f32acc(sacc[nt], qh[kk], kb[nt]);
                    mma_f32acc(sacc[nt], ql[kk], kb[nt]);
                }
            }

            // ---- causal mask ----
            if (kt >= 2*qt) {
                const int colb = kt*64 + 2*tig;
#pragma unroll
                for (int nt = 0; nt < 8; nt++) {
                    int c0 = colb + 8*nt, c1 = c0 + 1;
                    if (c0 > row0) sacc[nt][0] = -1e10f;
                    if (c1 > row0) sacc[nt][1] = -1e10f;
                    if (c0 > row1) sacc[nt][2] = -1e10f;
                    if (c1 > row1) sacc[nt][3] = -1e10f;
                }
            }

            // ---- online softmax ----
            float rm0 = -INFINITY, rm1 = -INFINITY;
#pragma unroll
            for (int nt = 0; nt < 8; nt++) {
                rm0 = fmaxf(rm0, fmaxf(sacc[nt][0], sacc[nt][1]));
                rm1 = fmaxf(rm1, fmaxf(sacc[nt][2], sacc[nt][3]));
            }
            rm0 = warp_rmax(rm0); rm1 = warp_rmax(rm1);
            float mn0 = fmaxf(m0, rm0), mn1 = fmaxf(m1, rm1);
            float cr0 = __expf(m0 - mn0), cr1 = __expf(m1 - mn1);
            m0 = mn0; m1 = mn1;
            float ps0 = 0.f, ps1 = 0.f;
#pragma unroll
            for (int nt = 0; nt < 8; nt++) {
                float p0 = __expf(sacc[nt][0] - mn0);
                float p1 = __expf(sacc[nt][1] - mn0);
                float p2 = __expf(sacc[nt][2] - mn1);
                float p3 = __expf(sacc[nt][3] - mn1);
                sacc[nt][0] = p0; sacc[nt][1] = p1; sacc[nt][2] = p2; sacc[nt][3] = p3;
                ps0 += p0 + p1; ps1 += p2 + p3;
            }
            ps0 = warp_rsum(ps0); ps1 = warp_rsum(ps1);
            l0 = l0*cr0 + ps0; l1 = l1*cr1 + ps1;
#pragma unroll
            for (int nt = 0; nt < 8; nt++) {
                oacc[nt][0] *= cr0; oacc[nt][1] *= cr0;
                oacc[nt][2] *= cr1; oacc[nt][3] *= cr1;
            }

            // ---- O += (Ph + Pl) * Vh ----
#pragma unroll
            for (int kk = 0; kk < 4; kk++) {
                uint32_t pah[4], pal[4];
#pragma unroll
                for (int jj = 0; jj < 2; jj++) {
                    const float* s4 = sacc[2*kk + jj];
                    uint32_t h01 = packh2(s4[0], s4[1]);
                    uint32_t h23 = packh2(s4[2], s4[3]);
                    float2 f01 = unpackh2(h01), f23 = unpackh2(h23);
                    pah[2*jj]   = h01;
                    pah[2*jj+1] = h23;
                    pal[2*jj]   = packh2(s4[0] - f01.x, s4[1] - f01.y);
                    pal[2*jj+1] = packh2(s4[2] - f23.x, s4[3] - f23.y);
                }
                const uint32_t vb0 = st + FTILE + (uint32_t)((16*kk + vrow_off)*FQSTR + vd_off)*2;
                uint32_t vb[8][2];
#pragma unroll
                for (int p = 0; p < 4; p++) {
                    uint32_t r[4];
                    ldm_x4_t(r, vb0 + (uint32_t)(16*p)*2);
                    vb[2*p][0] = r[0]; vb[2*p][1] = r[1];
                    vb[2*p+1][0] = r[2]; vb[2*p+1][1] = r[3];
                }
#pragma unroll
                for (int nt = 0; nt < 8; nt++) {
                    mma_f32acc(oacc[nt], pah, vb[nt]);
                    mma_f32acc(oacc[nt], pal, vb[nt]);
                }
            }
        }
        __syncthreads();
    }

    // ---- epilogue: normalize + split to f16 hi/lo ----
    const float inv0 = 1.f / l0, inv1 = 1.f / l1;
    const size_t r0g = (size_t)(b*SS + row0);
    const size_t r1g = (size_t)(b*SS + row1);
#pragma unroll
    for (int nt = 0; nt < 8; nt++) {
        const size_t col = hofs + 8*nt + 2*tig;
        float x0 = oacc[nt][0]*inv0, x1 = oacc[nt][1]*inv0;
        float x2 = oacc[nt][2]*inv1, x3 = oacc[nt][3]*inv1;
        uint32_t h01 = packh2(x0, x1), h23 = packh2(x2, x3);
        float2 f01 = unpackh2(h01), f23 = unpackh2(h23);
        uint32_t l01 = packh2(x0 - f01.x, x1 - f01.y);
        uint32_t l23 = packh2(x2 - f23.x, x3 - f23.y);
        *(uint32_t*)(AOh + r0g*DD + col) = h01;
        *(uint32_t*)(AOl + r0g*DD + col) = l01;
        *(uint32_t*)(AOh + r1g*DD + col) = h23;
        *(uint32_t*)(AOl + r1g*DD + col) = l23;
    }
}

// ---------------------------------------------------------------------------
extern "C" void kernel_launch(void* const* d_in, const int* in_sizes, int n_in,
                              void* d_out, int out_size)
{
    (void)in_sizes; (void)n_in; (void)out_size;
    const float* X  = (const float*)d_in[0];
    const float* Wq = (const float*)d_in[1];
    const float* Wk = (const float*)d_in[2];
    const float* Wv = (const float*)d_in[3];
    const float* Wo = (const float*)d_in[4];
    float* out = (float*)d_out;

    __half *Xh, *Xl, *Qh, *Ql, *Kh, *Vh, *AOh, *AOl, *LoSink;
    __half *Wqh, *Wkh, *Wvh, *Woh;
    cudaGetSymbolAddress((void**)&Xh,  g_Xh);
    cudaGetSymbolAddress((void**)&Xl,  g_Xl);
    cudaGetSymbolAddress((void**)&Qh,  g_Qh);
    cudaGetSymbolAddress((void**)&Ql,  g_Ql);
    cudaGetSymbolAddress((void**)&Kh,  g_Kh);
    cudaGetSymbolAddress((void**)&Vh,  g_Vh);
    cudaGetSymbolAddress((void**)&AOh, g_AOh);
    cudaGetSymbolAddress((void**)&AOl, g_AOl);
    cudaGetSymbolAddress((void**)&LoSink, g_LoSink);
    cudaGetSymbolAddress((void**)&Wqh, g_Wqh);
    cudaGetSymbolAddress((void**)&Wkh, g_Wkh);
    cudaGetSymbolAddress((void**)&Wvh, g_Wvh);
    cudaGetSymbolAddress((void**)&Woh, g_Woh);

    cudaFuncSetAttribute(gemm_f16x2<true>,  cudaFuncAttributeMaxDynamicSharedMemorySize, GEMM_SMEM);
    cudaFuncSetAttribute(gemm_f16x2<false>, cudaFuncAttributeMaxDynamicSharedMemorySize, GEMM_SMEM);
    cudaFuncSetAttribute(flash_mma, cudaFuncAttributeMaxDynamicSharedMemorySize, FLASH_SMEM);

    split_f16<<<512, 256>>>(X, Xh, Xl, GM*DD/4);
    conv_f16<<<256, 256>>>(Wq, Wqh, DD*DD/4);
    conv_f16<<<256, 256>>>(Wk, Wkh, DD*DD/4);
    conv_f16<<<256, 256>>>(Wv, Wvh, DD*DD/4);
    conv_f16<<<256, 256>>>(Wo, Woh, DD*DD/4);

    dim3 gg(GN/128, GM/128);   // (8, 32)
    gemm_f16x2<true><<<gg, 256, GEMM_SMEM>>>(Xh, Xl, Wqh, nullptr, Qh, Ql, 0.125f);
    gemm_f16x2<true><<<gg, 256, GEMM_SMEM>>>(Xh, Xl, Wkh, nullptr, Kh, LoSink, 1.0f);
    gemm_f16x2<true><<<gg, 256, GEMM_SMEM>>>(Xh, Xl, Wvh, nullptr, Vh, LoSink, 1.0f);

    flash_mma<<<dim3(SS/128, HH, BB), 256, FLASH_SMEM>>>(Qh, Ql, Kh, Vh, AOh, AOl);

    gemm_f16x2<false><<<gg, 256, GEMM_SMEM>>>(AOh, AOl, Woh, out, nullptr, nullptr, 1.0f);
}

// round 13
// speedup vs baseline: 1.1739x; 1.1739x over previous
#include <cuda_runtime.h>
#include <cuda_bf16.h>
#include <math.h>
#include <stdint.h>

#define BB 2
#define SS 2048
#define DD 1024
#define HH 16
#define GM (BB*SS)   /* 4096 */
#define GN DD
#define GK DD

// ---------------- scratch (allocation-free) ----------------
__device__ __nv_bfloat16 g_Xh[GM*DD],  g_Xl[GM*DD];
__device__ __nv_bfloat16 g_Qh[GM*DD],  g_Ql[GM*DD];
__device__ __nv_bfloat16 g_Kh[GM*DD],  g_Kl[GM*DD];
__device__ __nv_bfloat16 g_Vh[GM*DD],  g_Vl[GM*DD];
__device__ __nv_bfloat16 g_AOh[GM*DD], g_AOl[GM*DD];
__device__ __nv_bfloat16 g_Wqh[DD*DD], g_Wql[DD*DD];
__device__ __nv_bfloat16 g_Wkh[DD*DD], g_Wkl[DD*DD];
__device__ __nv_bfloat16 g_Wvh[DD*DD], g_Wvl[DD*DD];
__device__ __nv_bfloat16 g_Woh[DD*DD], g_Wol[DD*DD];

// ---------------- helpers ----------------
__device__ __forceinline__ uint32_t smem_u32(const void* p) {
    return (uint32_t)__cvta_generic_to_shared(p);
}
__device__ __forceinline__ void cp_async16(uint32_t dst, const void* src) {
    asm volatile("cp.async.cg.shared.global [%0], [%1], 16;" :: "r"(dst), "l"(src) : "memory");
}
__device__ __forceinline__ void cp_commit() {
    asm volatile("cp.async.commit_group;" ::: "memory");
}
template<int N>
__device__ __forceinline__ void cp_wait() {
    asm volatile("cp.async.wait_group %0;" :: "n"(N) : "memory");
}
__device__ __forceinline__ void ldm_x4(uint32_t* r, uint32_t addr) {
    asm volatile("ldmatrix.sync.aligned.m8n8.x4.shared.b16 {%0,%1,%2,%3}, [%4];"
                 : "=r"(r[0]), "=r"(r[1]), "=r"(r[2]), "=r"(r[3]) : "r"(addr));
}
__device__ __forceinline__ void ldm_x4_t(uint32_t* r, uint32_t addr) {
    asm volatile("ldmatrix.sync.aligned.m8n8.x4.trans.shared.b16 {%0,%1,%2,%3}, [%4];"
                 : "=r"(r[0]), "=r"(r[1]), "=r"(r[2]), "=r"(r[3]) : "r"(addr));
}
__device__ __forceinline__ void mma_bf16(float* c, const uint32_t* a, const uint32_t* b) {
    asm volatile("mma.sync.aligned.m16n8k16.row.col.f32.bf16.bf16.f32 "
                 "{%0,%1,%2,%3}, {%4,%5,%6,%7}, {%8,%9}, {%0,%1,%2,%3};"
                 : "+f"(c[0]), "+f"(c[1]), "+f"(c[2]), "+f"(c[3])
                 : "r"(a[0]), "r"(a[1]), "r"(a[2]), "r"(a[3]), "r"(b[0]), "r"(b[1]));
}
__device__ __forceinline__ uint32_t packbf(float lo, float hi) {
    uint32_t r; asm("cvt.rn.bf16x2.f32 %0, %1, %2;" : "=r"(r) : "f"(hi), "f"(lo)); return r;
}
__device__ __forceinline__ float bflo(uint32_t r) { return __uint_as_float(r << 16); }
__device__ __forceinline__ float bfhi(uint32_t r) { return __uint_as_float(r & 0xffff0000u); }
__device__ __forceinline__ float warp_rmax(float x) {
    x = fmaxf(x, __shfl_xor_sync(0xffffffffu, x, 1));
    x = fmaxf(x, __shfl_xor_sync(0xffffffffu, x, 2));
    return x;
}
__device__ __forceinline__ float warp_rsum(float x) {
    x += __shfl_xor_sync(0xffffffffu, x, 1);
    x += __shfl_xor_sync(0xffffffffu, x, 2);
    return x;
}

// ---------------- split fp32 -> bf16 hi/lo ----------------
__global__ void split_bf16(const float* __restrict__ in, __nv_bfloat16* __restrict__ hi,
                           __nv_bfloat16* __restrict__ lo, int n4)
{
    int i = blockIdx.x*blockDim.x + threadIdx.x;
    int stride = gridDim.x*blockDim.x;
    const float4* in4 = (const float4*)in;
    uint32_t* h2 = (uint32_t*)hi;
    uint32_t* l2 = (uint32_t*)lo;
    for (; i < n4; i += stride) {
        float4 v = in4[i];
        uint32_t h01 = packbf(v.x, v.y), h23 = packbf(v.z, v.w);
        uint32_t l01 = packbf(v.x - bflo(h01), v.y - bfhi(h01));
        uint32_t l23 = packbf(v.z - bflo(h23), v.w - bfhi(h23));
        h2[i*2] = h01; h2[i*2+1] = h23;
        l2[i*2] = l01; l2[i*2+1] = l23;
    }
}

// ---------------- bf16x2 GEMM core: C = alpha*(A @ B^T), tile 64x128 ----------------
// 2-stage cp.async, 2 CTAs/SM (smem 110592B), 8 warps as 2(M)x4(N), warp tile 32x32.
#define KCH 64
#define NCH (GK/KCH)
#define SRE 72
#define SRB (SRE*2)                 /* 144 B per 64-half row */
#define AT_B (64*SRB)               /* 9216  */
#define BT_B (128*SRB)              /* 18432 */
#define OFF_AH 0
#define OFF_AL (AT_B)
#define OFF_BH (2*AT_B)
#define OFF_BL (2*AT_B + BT_B)
#define STAGE64 (2*AT_B + 2*BT_B)   /* 55296 */
#define GEMM_SMEM (2*STAGE64)       /* 110592 */

template<bool SPLIT>
__device__ __forceinline__ void gemm64_core(
    const __nv_bfloat16* __restrict__ Ah, const __nv_bfloat16* __restrict__ Al,
    const __nv_bfloat16* __restrict__ Bh, const __nv_bfloat16* __restrict__ Bl,
    float* __restrict__ Cf, __nv_bfloat16* __restrict__ Chi, __nv_bfloat16* __restrict__ Clo,
    float alpha, int cRow, int cCol, char* smem)
{
    const uint32_t sb = smem_u32(smem);
    const int tid  = threadIdx.x;
    const int lane = tid & 31;
    const int warp = tid >> 5;
    const int wm   = warp & 1;        // 0..1 -> 32 rows
    const int wn   = warp >> 1;       // 0..3 -> 32 cols

    const int lr = tid >> 3;          // 0..31
    const int lc = tid & 7;           // quad within row

    const uint32_t aOff = (uint32_t)((lane & 15)*SRB + (lane >> 4)*16 + wm*32*SRB);
    const uint32_t bOff = (uint32_t)(((lane & 7) + ((lane >> 4) << 3))*SRB
                                     + ((lane >> 3) & 1)*16 + wn*32*SRB);

    float acc[2][4][4];
#pragma unroll
    for (int mt = 0; mt < 2; mt++)
#pragma unroll
        for (int nt = 0; nt < 4; nt++)
#pragma unroll
            for (int q = 0; q < 4; q++) acc[mt][nt][q] = 0.f;

    auto issue_chunk = [&](int j, int s) {
        const uint32_t st = sb + (uint32_t)s*STAGE64;
        const int k0 = j*KCH;
#pragma unroll
        for (int r = 0; r < 2; r++) {
            cp_async16(st + OFF_AH + (lr + 32*r)*SRB + lc*16,
                       Ah + (size_t)(cRow + lr + 32*r)*GK + k0 + lc*8);
            cp_async16(st + OFF_AL + (lr + 32*r)*SRB + lc*16,
                       Al + (size_t)(cRow + lr + 32*r)*GK + k0 + lc*8);
        }
#pragma unroll
        for (int r = 0; r < 4; r++) {
            cp_async16(st + OFF_BH + (lr + 32*r)*SRB + lc*16,
                       Bh + (size_t)(cCol + lr + 32*r)*GK + k0 + lc*8);
            cp_async16(st + OFF_BL + (lr + 32*r)*SRB + lc*16,
                       Bl + (size_t)(cCol + lr + 32*r)*GK + k0 + lc*8);
        }
        cp_commit();
    };

    issue_chunk(0, 0);

    for (int j = 0; j < NCH; j++) {
        if (j + 1 < NCH) { issue_chunk(j + 1, (j + 1) & 1); cp_wait<1>(); }
        else             { cp_wait<0>(); }
        __syncthreads();

        const uint32_t stg = sb + (uint32_t)(j & 1)*STAGE64;
        const uint32_t aBH = stg + OFF_AH + aOff;
        const uint32_t aBL = stg + OFF_AL + aOff;
        const uint32_t bBH = stg + OFF_BH + bOff;
        const uint32_t bBL = stg + OFF_BL + bOff;
#pragma unroll
        for (int k16 = 0; k16 < 4; k16++) {
            uint32_t ah2[2][4], al2[2][4], bh2[2][4], bl2[2][4];
            ldm_x4(ah2[0], aBH + k16*32);
            ldm_x4(ah2[1], aBH + k16*32 + 16*SRB);
            ldm_x4(al2[0], aBL + k16*32);
            ldm_x4(al2[1], aBL + k16*32 + 16*SRB);
            ldm_x4(bh2[0], bBH + k16*32);
            ldm_x4(bh2[1], bBH + k16*32 + 16*SRB);
            ldm_x4(bl2[0], bBL + k16*32);
            ldm_x4(bl2[1], bBL + k16*32 + 16*SRB);
#pragma unroll
            for (int mt = 0; mt < 2; mt++)
#pragma unroll
                for (int ng = 0; ng < 2; ng++) {
                    mma_bf16(acc[mt][2*ng+0], ah2[mt], &bh2[ng][0]);
                    mma_bf16(acc[mt][2*ng+1], ah2[mt], &bh2[ng][2]);
                    mma_bf16(acc[mt][2*ng+0], al2[mt], &bh2[ng][0]);
                    mma_bf16(acc[mt][2*ng+1], al2[mt], &bh2[ng][2]);
                    mma_bf16(acc[mt][2*ng+0], ah2[mt], &bl2[ng][0]);
                    mma_bf16(acc[mt][2*ng+1], ah2[mt], &bl2[ng][2]);
                }
        }
        __syncthreads();
    }

    const int gid = lane >> 2, tig = lane & 3;
#pragma unroll
    for (int mt = 0; mt < 2; mt++) {
        const int m0 = cRow + wm*32 + mt*16 + gid;
#pragma unroll
        for (int nt = 0; nt < 4; nt++) {
            const int n = cCol + wn*32 + nt*8 + tig*2;
            float v0 = acc[mt][nt][0]*alpha, v1 = acc[mt][nt][1]*alpha;
            float v2 = acc[mt][nt][2]*alpha, v3 = acc[mt][nt][3]*alpha;
            if (SPLIT) {
                uint32_t h01 = packbf(v0, v1), h23 = packbf(v2, v3);
                uint32_t l01 = packbf(v0 - bflo(h01), v1 - bfhi(h01));
                uint32_t l23 = packbf(v2 - bflo(h23), v3 - bfhi(h23));
                *(uint32_t*)(Chi + (size_t)m0*GN + n)     = h01;
                *(uint32_t*)(Clo + (size_t)m0*GN + n)     = l01;
                *(uint32_t*)(Chi + (size_t)(m0+8)*GN + n) = h23;
                *(uint32_t*)(Clo + (size_t)(m0+8)*GN + n) = l23;
            } else {
                float2 a0 = {v0, v1}, a1 = {v2, v3};
                *(float2*)(Cf + (size_t)m0*GN + n)     = a0;
                *(float2*)(Cf + (size_t)(m0+8)*GN + n) = a1;
            }
        }
    }
}

// Fused Q/K/V projection: blockIdx.z selects weight + destination.
__global__ __launch_bounds__(256, 2)
void gemm_qkv(const __nv_bfloat16* __restrict__ Xh, const __nv_bfloat16* __restrict__ Xl,
              const __nv_bfloat16* __restrict__ Wqh, const __nv_bfloat16* __restrict__ Wql,
              const __nv_bfloat16* __restrict__ Wkh, const __nv_bfloat16* __restrict__ Wkl,
              const __nv_bfloat16* __restrict__ Wvh, const __nv_bfloat16* __restrict__ Wvl,
              __nv_bfloat16* __restrict__ Qh, __nv_bfloat16* __restrict__ Ql,
              __nv_bfloat16* __restrict__ Kh, __nv_bfloat16* __restrict__ Kl,
              __nv_bfloat16* __restrict__ Vh, __nv_bfloat16* __restrict__ Vl)
{
    extern __shared__ char smem[];
    const int cRow = blockIdx.y << 6;
    const int cCol = blockIdx.x << 7;
    const int z = blockIdx.z;
    const __nv_bfloat16 *Bh, *Bl;
    __nv_bfloat16 *Chi, *Clo;
    float alpha;
    if (z == 0)      { Bh = Wqh; Bl = Wql; Chi = Qh; Clo = Ql; alpha = 0.125f; }
    else if (z == 1) { Bh = Wkh; Bl = Wkl; Chi = Kh; Clo = Kl; alpha = 1.0f; }
    else             { Bh = Wvh; Bl = Wvl; Chi = Vh; Clo = Vl; alpha = 1.0f; }
    gemm64_core<true>(Xh, Xl, Bh, Bl, nullptr, Chi, Clo, alpha, cRow, cCol, smem);
}

__global__ __launch_bounds__(256, 2)
void gemm_out(const __nv_bfloat16* __restrict__ AOh, const __nv_bfloat16* __restrict__ AOl,
              const __nv_bfloat16* __restrict__ Woh, const __nv_bfloat16* __restrict__ Wol,
              float* __restrict__ out)
{
    extern __shared__ char smem[];
    gemm64_core<false>(AOh, AOl, Woh, Wol, out, nullptr, nullptr, 1.0f,
                       blockIdx.y << 6, blockIdx.x << 7, smem);
}

// ---------------------------------------------------------------------------
// Flash attention on mma.sync, causal, bf16x2 3-pass. 3-stage KV pipeline.
// (Proven R5 version, unchanged.)
// ---------------------------------------------------------------------------
#define FQSTR 72
#define FTILE (64*FQSTR*2)
#define FSTAGE (4*FTILE)                         /* 36864 */
#define FLASH_SMEM (2*128*FQSTR*2 + 3*FSTAGE)    /* 147456 */

__global__ __launch_bounds__(256, 1)
void flash_mma(const __nv_bfloat16* __restrict__ Qh_, const __nv_bfloat16* __restrict__ Ql_,
               const __nv_bfloat16* __restrict__ Kh_, const __nv_bfloat16* __restrict__ Kl_,
               const __nv_bfloat16* __restrict__ Vh_, const __nv_bfloat16* __restrict__ Vl_,
               __nv_bfloat16* __restrict__ AOh, __nv_bfloat16* __restrict__ AOl)
{
    extern __shared__ char smc[];
    const int qt  = (int)gridDim.x - 1 - (int)blockIdx.x;
    const int h   = blockIdx.y, b = blockIdx.z;
    const int tid = threadIdx.x;
    const int lane = tid & 31, w = tid >> 5;
    const int qbase = qt*128;
    const int ktmax = 2*qt + 1;

    const uint32_t sb  = smem_u32(smc);
    const uint32_t uQh = sb;
    const uint32_t uQl = sb + 128*FQSTR*2;
    const uint32_t uKV = sb + 2*128*FQSTR*2;

    const __nv_bfloat16* qsrc[2]  = {Qh_, Ql_};
    const __nv_bfloat16* kvsrc[4] = {Kh_, Kl_, Vh_, Vl_};
    const size_t hofs = (size_t)h*64;

    auto load_kv = [&](int kt, int s) {
#pragma unroll
        for (int i = 0; i < 8; i++) {
            int id = tid + i*256;
            int a = id >> 9, r = (id >> 3) & 63, c = id & 7;
            const __nv_bfloat16* g = kvsrc[a] + (size_t)(b*SS + kt*64 + r)*DD + hofs + c*8;
            cp_async16(uKV + s*FSTAGE + a*FTILE + (uint32_t)(r*FQSTR + c*8)*2, g);
        }
    };

#pragma unroll
    for (int i = 0; i < 8; i++) {
        int id = tid + i*256;
        int a = id >> 10, r = (id >> 3) & 127, c = id & 7;
        const __nv_bfloat16* g = qsrc[a] + (size_t)(b*SS + qbase + r)*DD + hofs + c*8;
        cp_async16((a ? uQl : uQh) + (uint32_t)(r*FQSTR + c*8)*2, g);
    }
    load_kv(0, 0);
    cp_commit();
    load_kv(1, 1);
    cp_commit();

    const int gid = lane >> 2, tig = lane & 3;
    const int qrow_off = ((lane>>3)&1)*8 + (lane&7);
    const int qd_off   = (lane>>4)*8;
    const int krow_off = (lane>>4)*8 + (lane&7);
    const int kd_off   = ((lane>>3)&1)*8;
    const int vrow_off = ((lane>>3)&1)*8 + (lane&7);
    const int vd_off   = (lane>>4)*8;

    uint32_t qh[4][4], ql[4][4];

    float m0 = -INFINITY, m1 = -INFINITY, l0 = 0.f, l1 = 0.f;
    float oacc[8][4];
#pragma unroll
    for (int nt = 0; nt < 8; nt++)
#pragma unroll
        for (int q = 0; q < 4; q++) oacc[nt][q] = 0.f;

    const int row0 = qbase + 16*w + gid;
    const int row1 = row0 + 8;

    for (int kt = 0; kt <= ktmax; kt++) {
        if (kt + 2 <= ktmax) { load_kv(kt + 2, (kt + 2) % 3); cp_commit(); }
        if (kt + 2 <= ktmax)      cp_wait<2>();
        else if (kt + 1 <= ktmax) cp_wait<1>();
        else                      cp_wait<0>();
        __syncthreads();

        if (kt == 0) {
            uint32_t ah = uQh + (uint32_t)((16*w + qrow_off)*FQSTR + qd_off)*2;
            uint32_t al = uQl + (uint32_t)((16*w + qrow_off)*FQSTR + qd_off)*2;
#pragma unroll
            for (int kk = 0; kk < 4; kk++) {
                ldm_x4(qh[kk], ah + kk*32);
                ldm_x4(ql[kk], al + kk*32);
            }
        }

        const uint32_t st = uKV + (uint32_t)(kt % 3)*FSTAGE;
        const bool active = (kt*64 <= qbase + 16*w + 15);
        if (active) {
            float sacc[8][4];
#pragma unroll
            for (int nt = 0; nt < 8; nt++)
#pragma unroll
                for (int q = 0; q < 4; q++) sacc[nt][q] = 0.f;

            // ---- S = Qh*Kh + Ql*Kh + Qh*Kl ----
#pragma unroll
            for (int kk = 0; kk < 4; kk++) {
                const uint32_t kb0 = st + (uint32_t)(krow_off*FQSTR + kd_off + 16*kk)*2;
                uint32_t kb[8][2], kl[8][2];
#pragma unroll
                for (int p = 0; p < 4; p++) {
                    uint32_t r[4];
                    ldm_x4(r, kb0 + (uint32_t)(16*p*FQSTR)*2);
                    kb[2*p][0] = r[0]; kb[2*p][1] = r[1];
                    kb[2*p+1][0] = r[2]; kb[2*p+1][1] = r[3];
                    ldm_x4(r, kb0 + FTILE + (uint32_t)(16*p*FQSTR)*2);
                    kl[2*p][0] = r[0]; kl[2*p][1] = r[1];
                    kl[2*p+1][0] = r[2]; kl[2*p+1][1] = r[3];
                }
#pragma unroll
                for (int nt = 0; nt < 8; nt++) {
                    mma_bf16(sacc[nt], qh[kk], kb[nt]);
                    mma_bf16(sacc[nt], ql[kk], kb[nt]);
                    mma_bf16(sacc[nt], qh[kk], kl[nt]);
                }
            }

            if (kt >= 2*qt) {
                const int colb = kt*64 + 2*tig;
#pragma unroll
                for (int nt = 0; nt < 8; nt++) {
                    int c0 = colb + 8*nt, c1 = c0 + 1;
                    if (c0 > row0) sacc[nt][0] = -1e10f;
                    if (c1 > row0) sacc[nt][1] = -1e10f;
                    if (c0 > row1) sacc[nt][2] = -1e10f;
                    if (c1 > row1) sacc[nt][3] = -1e10f;
                }
            }

            float rm0 = -INFINITY, rm1 = -INFINITY;
#pragma unroll
            for (int nt = 0; nt < 8; nt++) {
                rm0 = fmaxf(rm0, fmaxf(sacc[nt][0], sacc[nt][1]));
                rm1 = fmaxf(rm1, fmaxf(sacc[nt][2], sacc[nt][3]));
            }
            rm0 = warp_rmax(rm0); rm1 = warp_rmax(rm1);
            float mn0 = fmaxf(m0, rm0), mn1 = fmaxf(m1, rm1);
            float cr0 = __expf(m0 - mn0), cr1 = __expf(m1 - mn1);
            m0 = mn0; m1 = mn1;
            float ps0 = 0.f, ps1 = 0.f;
#pragma unroll
            for (int nt = 0; nt < 8; nt++) {
                float p0 = __expf(sacc[nt][0] - mn0);
                float p1 = __expf(sacc[nt][1] - mn0);
                float p2 = __expf(sacc[nt][2] - mn1);
                float p3 = __expf(sacc[nt][3] - mn1);
                sacc[nt][0] = p0; sacc[nt][1] = p1; sacc[nt][2] = p2; sacc[nt][3] = p3;
                ps0 += p0 + p1; ps1 += p2 + p3;
            }
            ps0 = warp_rsum(ps0); ps1 = warp_rsum(ps1);
            l0 = l0*cr0 + ps0; l1 = l1*cr1 + ps1;
#pragma unroll
            for (int nt = 0; nt < 8; nt++) {
                oacc[nt][0] *= cr0; oacc[nt][1] *= cr0;
                oacc[nt][2] *= cr1; oacc[nt][3] *= cr1;
            }

            // ---- O += Ph*Vh + Pl*Vh + Ph*Vl ----
#pragma unroll
            for (int kk = 0; kk < 4; kk++) {
                uint32_t pah[4], pal[4];
#pragma unroll
                for (int jj = 0; jj < 2; jj++) {
                    const float* s4 = sacc[2*kk + jj];
                    uint32_t h01 = packbf(s4[0], s4[1]);
                    uint32_t h23 = packbf(s4[2], s4[3]);
                    pah[2*jj]   = h01;
                    pah[2*jj+1] = h23;
                    pal[2*jj]   = packbf(s4[0] - bflo(h01), s4[1] - bfhi(h01));
                    pal[2*jj+1] = packbf(s4[2] - bflo(h23), s4[3] - bfhi(h23));
                }
                const uint32_t vb0 = st + 2*FTILE + (uint32_t)((16*kk + vrow_off)*FQSTR + vd_off)*2;
                uint32_t vb[8][2], vl[8][2];
#pragma unroll
                for (int p = 0; p < 4; p++) {
                    uint32_t r[4];
                    ldm_x4_t(r, vb0 + (uint32_t)(16*p)*2);
                    vb[2*p][0] = r[0]; vb[2*p][1] = r[1];
                    vb[2*p+1][0] = r[2]; vb[2*p+1][1] = r[3];
                    ldm_x4_t(r, vb0 + FTILE + (uint32_t)(16*p)*2);
                    vl[2*p][0] = r[0]; vl[2*p][1] = r[1];
                    vl[2*p+1][0] = r[2]; vl[2*p+1][1] = r[3];
                }
#pragma unroll
                for (int nt = 0; nt < 8; nt++) {
                    mma_bf16(oacc[nt], pah, vb[nt]);
                    mma_bf16(oacc[nt], pal, vb[nt]);
                    mma_bf16(oacc[nt], pah, vl[nt]);
                }
            }
        }
        __syncthreads();
    }

    const float inv0 = 1.f / l0, inv1 = 1.f / l1;
    const size_t r0g = (size_t)(b*SS + row0);
    const size_t r1g = (size_t)(b*SS + row1);
#pragma unroll
    for (int nt = 0; nt < 8; nt++) {
        const size_t col = hofs + 8*nt + 2*tig;
        float x0 = oacc[nt][0]*inv0, x1 = oacc[nt][1]*inv0;
        float x2 = oacc[nt][2]*inv1, x3 = oacc[nt][3]*inv1;
        uint32_t h01 = packbf(x0, x1), h23 = packbf(x2, x3);
        uint32_t l01 = packbf(x0 - bflo(h01), x1 - bfhi(h01));
        uint32_t l23 = packbf(x2 - bflo(h23), x3 - bfhi(h23));
        *(uint32_t*)(AOh + r0g*DD + col) = h01;
        *(uint32_t*)(AOl + r0g*DD + col) = l01;
        *(uint32_t*)(AOh + r1g*DD + col) = h23;
        *(uint32_t*)(AOl + r1g*DD + col) = l23;
    }
}

// ---------------------------------------------------------------------------
extern "C" void kernel_launch(void* const* d_in, const int* in_sizes, int n_in,
                              void* d_out, int out_size)
{
    (void)in_sizes; (void)n_in; (void)out_size;
    const float* X  = (const float*)d_in[0];
    const float* Wq = (const float*)d_in[1];
    const float* Wk = (const float*)d_in[2];
    const float* Wv = (const float*)d_in[3];
    const float* Wo = (const float*)d_in[4];
    float* out = (float*)d_out;

    __nv_bfloat16 *Xh, *Xl, *Qh, *Ql, *Kh, *Kl, *Vh, *Vl, *AOh, *AOl;
    __nv_bfloat16 *Wqh, *Wql, *Wkh, *Wkl, *Wvh, *Wvl, *Woh, *Wol;
    cudaGetSymbolAddress((void**)&Xh,  g_Xh);
    cudaGetSymbolAddress((void**)&Xl,  g_Xl);
    cudaGetSymbolAddress((void**)&Qh,  g_Qh);
    cudaGetSymbolAddress((void**)&Ql,  g_Ql);
    cudaGetSymbolAddress((void**)&Kh,  g_Kh);
    cudaGetSymbolAddress((void**)&Kl,  g_Kl);
    cudaGetSymbolAddress((void**)&Vh,  g_Vh);
    cudaGetSymbolAddress((void**)&Vl,  g_Vl);
    cudaGetSymbolAddress((void**)&AOh, g_AOh);
    cudaGetSymbolAddress((void**)&AOl, g_AOl);
    cudaGetSymbolAddress((void**)&Wqh, g_Wqh);
    cudaGetSymbolAddress((void**)&Wql, g_Wql);
    cudaGetSymbolAddress((void**)&Wkh, g_Wkh);
    cudaGetSymbolAddress((void**)&Wkl, g_Wkl);
    cudaGetSymbolAddress((void**)&Wvh, g_Wvh);
    cudaGetSymbolAddress((void**)&Wvl, g_Wvl);
    cudaGetSymbolAddress((void**)&Woh, g_Woh);
    cudaGetSymbolAddress((void**)&Wol, g_Wol);

    cudaFuncSetAttribute(gemm_qkv, cudaFuncAttributeMaxDynamicSharedMemorySize, GEMM_SMEM);
    cudaFuncSetAttribute(gemm_out, cudaFuncAttributeMaxDynamicSharedMemorySize, GEMM_SMEM);
    cudaFuncSetAttribute(flash_mma, cudaFuncAttributeMaxDynamicSharedMemorySize, FLASH_SMEM);

    // launches 1-5 (so the -s 5 ncu window lands on gemm_qkv)
    split_bf16<<<512, 256>>>(X,  Xh,  Xl,  GM*DD/4);
    split_bf16<<<256, 256>>>(Wq, Wqh, Wql, DD*DD/4);
    split_bf16<<<256, 256>>>(Wk, Wkh, Wkl, DD*DD/4);
    split_bf16<<<256, 256>>>(Wv, Wvh, Wvl, DD*DD/4);
    split_bf16<<<256, 256>>>(Wo, Woh, Wol, DD*DD/4);

    // launch 6: fused Q/K/V projections, 64x128 tiles, 2 CTAs/SM
    gemm_qkv<<<dim3(GN/128, GM/64, 3), 256, GEMM_SMEM>>>(
        Xh, Xl, Wqh, Wql, Wkh, Wkl, Wvh, Wvl, Qh, Ql, Kh, Kl, Vh, Vl);

    // launch 7: flash attention
    flash_mma<<<dim3(SS/128, HH, BB), 256, FLASH_SMEM>>>(Qh, Ql, Kh, Kl, Vh, Vl, AOh, AOl);

    // launch 8: output projection
    gemm_out<<<dim3(GN/128, GM/64, 1), 256, GEMM_SMEM>>>(AOh, AOl, Woh, Wol, out);
}

// round 14
// speedup vs baseline: 1.7631x; 1.5020x over previous
#include <cuda_runtime.h>
#include <cuda_fp16.h>
#include <math.h>
#include <stdint.h>

#define BB 2
#define SS 2048
#define DD 1024
#define HH 16
#define GM (BB*SS)   /* 4096 */
#define GN DD
#define GK DD

// ---------------- scratch (allocation-free) ----------------
__device__ __half g_Xh[GM*DD],  g_Xl[GM*DD];
__device__ __half g_Qh[GM*DD],  g_Ql[GM*DD];
__device__ __half g_Kh[GM*DD];
__device__ __half g_Vh[GM*DD];
__device__ __half g_AOh[GM*DD], g_AOl[GM*DD];
__device__ __half g_LoSink[GM*DD];
__device__ __half g_Wqh[DD*DD];
__device__ __half g_Wkh[DD*DD];
__device__ __half g_Wvh[DD*DD];
__device__ __half g_Woh[DD*DD];

// ---------------- helpers ----------------
__device__ __forceinline__ uint32_t smem_u32(const void* p) {
    return (uint32_t)__cvta_generic_to_shared(p);
}
__device__ __forceinline__ void cp_async16(uint32_t dst, const void* src) {
    asm volatile("cp.async.cg.shared.global [%0], [%1], 16;" :: "r"(dst), "l"(src) : "memory");
}
__device__ __forceinline__ void cp_commit() {
    asm volatile("cp.async.commit_group;" ::: "memory");
}
template<int N>
__device__ __forceinline__ void cp_wait() {
    asm volatile("cp.async.wait_group %0;" :: "n"(N) : "memory");
}
__device__ __forceinline__ void ldm_x4(uint32_t* r, uint32_t addr) {
    asm volatile("ldmatrix.sync.aligned.m8n8.x4.shared.b16 {%0,%1,%2,%3}, [%4];"
                 : "=r"(r[0]), "=r"(r[1]), "=r"(r[2]), "=r"(r[3]) : "r"(addr));
}
__device__ __forceinline__ void ldm_x4_t(uint32_t* r, uint32_t addr) {
    asm volatile("ldmatrix.sync.aligned.m8n8.x4.trans.shared.b16 {%0,%1,%2,%3}, [%4];"
                 : "=r"(r[0]), "=r"(r[1]), "=r"(r[2]), "=r"(r[3]) : "r"(addr));
}
__device__ __forceinline__ void mma_f32acc(float* c, const uint32_t* a, const uint32_t* b) {
    asm volatile("mma.sync.aligned.m16n8k16.row.col.f32.f16.f16.f32 "
                 "{%0,%1,%2,%3}, {%4,%5,%6,%7}, {%8,%9}, {%0,%1,%2,%3};"
                 : "+f"(c[0]), "+f"(c[1]), "+f"(c[2]), "+f"(c[3])
                 : "r"(a[0]), "r"(a[1]), "r"(a[2]), "r"(a[3]), "r"(b[0]), "r"(b[1]));
}
__device__ __forceinline__ uint32_t packh2(float a, float b) {
    __half2 h = __floats2half2_rn(a, b);
    return *(uint32_t*)&h;
}
__device__ __forceinline__ float2 unpackh2(uint32_t r) {
    __half2 h = *(__half2*)&r;
    return __half22float2(h);
}
__device__ __forceinline__ float warp_rmax(float x) {
    x = fmaxf(x, __shfl_xor_sync(0xffffffffu, x, 1));
    x = fmaxf(x, __shfl_xor_sync(0xffffffffu, x, 2));
    return x;
}
__device__ __forceinline__ float warp_rsum(float x) {
    x += __shfl_xor_sync(0xffffffffu, x, 1);
    x += __shfl_xor_sync(0xffffffffu, x, 2);
    return x;
}

// ---------------- conversions ----------------
__global__ void split_f16(const float* __restrict__ in, __half* __restrict__ hi,
                          __half* __restrict__ lo, int n4)
{
    int i = blockIdx.x*blockDim.x + threadIdx.x;
    int stride = gridDim.x*blockDim.x;
    const float4* in4 = (const float4*)in;
    uint32_t* h2 = (uint32_t*)hi;
    uint32_t* l2 = (uint32_t*)lo;
    for (; i < n4; i += stride) {
        float4 v = in4[i];
        uint32_t h01 = packh2(v.x, v.y), h23 = packh2(v.z, v.w);
        float2 f01 = unpackh2(h01), f23 = unpackh2(h23);
        uint32_t l01 = packh2(v.x - f01.x, v.y - f01.y);
        uint32_t l23 = packh2(v.z - f23.x, v.w - f23.y);
        h2[i*2] = h01; h2[i*2+1] = h23;
        l2[i*2] = l01; l2[i*2+1] = l23;
    }
}
__global__ void conv_f16(const float* __restrict__ in, __half* __restrict__ hi, int n4)
{
    int i = blockIdx.x*blockDim.x + threadIdx.x;
    int stride = gridDim.x*blockDim.x;
    const float4* in4 = (const float4*)in;
    uint32_t* h2 = (uint32_t*)hi;
    for (; i < n4; i += stride) {
        float4 v = in4[i];
        h2[i*2]   = packh2(v.x, v.y);
        h2[i*2+1] = packh2(v.z, v.w);
    }
}

// ---------------- 2-pass f16 GEMM core: C = alpha*((Ah+Al) @ Bh^T), tile 64x128 ----------------
// Stage = Ah(9216) + Al(9216) + Bh(18432) = 36864; 2-stage = 73728 -> 3 CTAs/SM.
#define KCH 64
#define NCH (GK/KCH)
#define SRE 72
#define SRB (SRE*2)
#define AT_B (64*SRB)               /* 9216  */
#define BT_B (128*SRB)              /* 18432 */
#define OFF_AH 0
#define OFF_AL (AT_B)
#define OFF_BH (2*AT_B)
#define STAGE64 (2*AT_B + BT_B)     /* 36864 */
#define GEMM_SMEM (2*STAGE64)       /* 73728 */

template<bool SPLIT>
__device__ __forceinline__ void gemm64_core(
    const __half* __restrict__ Ah, const __half* __restrict__ Al,
    const __half* __restrict__ Bh,
    float* __restrict__ Cf, __half* __restrict__ Chi, __half* __restrict__ Clo,
    float alpha, int cRow, int cCol, char* smem)
{
    const uint32_t sb = smem_u32(smem);
    const int tid  = threadIdx.x;
    const int lane = tid & 31;
    const int warp = tid >> 5;
    const int wm   = warp & 1;        // 0..1 -> 32 rows
    const int wn   = warp >> 1;       // 0..3 -> 32 cols

    const int lr = tid >> 3;          // 0..31
    const int lc = tid & 7;

    const uint32_t aOff = (uint32_t)((lane & 15)*SRB + (lane >> 4)*16 + wm*32*SRB);
    const uint32_t bOff = (uint32_t)(((lane & 7) + ((lane >> 4) << 3))*SRB
                                     + ((lane >> 3) & 1)*16 + wn*32*SRB);

    float acc[2][4][4];
#pragma unroll
    for (int mt = 0; mt < 2; mt++)
#pragma unroll
        for (int nt = 0; nt < 4; nt++)
#pragma unroll
            for (int q = 0; q < 4; q++) acc[mt][nt][q] = 0.f;

    auto issue_chunk = [&](int j, int s) {
        const uint32_t st = sb + (uint32_t)s*STAGE64;
        const int k0 = j*KCH;
#pragma unroll
        for (int r = 0; r < 2; r++) {
            cp_async16(st + OFF_AH + (lr + 32*r)*SRB + lc*16,
                       Ah + (size_t)(cRow + lr + 32*r)*GK + k0 + lc*8);
            cp_async16(st + OFF_AL + (lr + 32*r)*SRB + lc*16,
                       Al + (size_t)(cRow + lr + 32*r)*GK + k0 + lc*8);
        }
#pragma unroll
        for (int r = 0; r < 4; r++)
            cp_async16(st + OFF_BH + (lr + 32*r)*SRB + lc*16,
                       Bh + (size_t)(cCol + lr + 32*r)*GK + k0 + lc*8);
        cp_commit();
    };

    issue_chunk(0, 0);

    for (int j = 0; j < NCH; j++) {
        if (j + 1 < NCH) { issue_chunk(j + 1, (j + 1) & 1); cp_wait<1>(); }
        else             { cp_wait<0>(); }
        __syncthreads();

        const uint32_t stg = sb + (uint32_t)(j & 1)*STAGE64;
        const uint32_t aBH = stg + OFF_AH + aOff;
        const uint32_t aBL = stg + OFF_AL + aOff;
        const uint32_t bBH = stg + OFF_BH + bOff;
#pragma unroll
        for (int k16 = 0; k16 < 4; k16++) {
            uint32_t ah2[2][4], al2[2][4], bh2[2][4];
            ldm_x4(ah2[0], aBH + k16*32);
            ldm_x4(ah2[1], aBH + k16*32 + 16*SRB);
            ldm_x4(al2[0], aBL + k16*32);
            ldm_x4(al2[1], aBL + k16*32 + 16*SRB);
            ldm_x4(bh2[0], bBH + k16*32);
            ldm_x4(bh2[1], bBH + k16*32 + 16*SRB);
#pragma unroll
            for (int mt = 0; mt < 2; mt++)
#pragma unroll
                for (int ng = 0; ng < 2; ng++) {
                    mma_f32acc(acc[mt][2*ng+0], ah2[mt], &bh2[ng][0]);
                    mma_f32acc(acc[mt][2*ng+1], ah2[mt], &bh2[ng][2]);
                    mma_f32acc(acc[mt][2*ng+0], al2[mt], &bh2[ng][0]);
                    mma_f32acc(acc[mt][2*ng+1], al2[mt], &bh2[ng][2]);
                }
        }
        __syncthreads();
    }

    const int gid = lane >> 2, tig = lane & 3;
#pragma unroll
    for (int mt = 0; mt < 2; mt++) {
        const int m0 = cRow + wm*32 + mt*16 + gid;
#pragma unroll
        for (int nt = 0; nt < 4; nt++) {
            const int n = cCol + wn*32 + nt*8 + tig*2;
            float v0 = acc[mt][nt][0]*alpha, v1 = acc[mt][nt][1]*alpha;
            float v2 = acc[mt][nt][2]*alpha, v3 = acc[mt][nt][3]*alpha;
            if (SPLIT) {
                uint32_t h01 = packh2(v0, v1), h23 = packh2(v2, v3);
                float2 f01 = unpackh2(h01), f23 = unpackh2(h23);
                uint32_t l01 = packh2(v0 - f01.x, v1 - f01.y);
                uint32_t l23 = packh2(v2 - f23.x, v3 - f23.y);
                *(uint32_t*)(Chi + (size_t)m0*GN + n)     = h01;
                *(uint32_t*)(Clo + (size_t)m0*GN + n)     = l01;
                *(uint32_t*)(Chi + (size_t)(m0+8)*GN + n) = h23;
                *(uint32_t*)(Clo + (size_t)(m0+8)*GN + n) = l23;
            } else {
                float2 a0 = {v0, v1}, a1 = {v2, v3};
                *(float2*)(Cf + (size_t)m0*GN + n)     = a0;
                *(float2*)(Cf + (size_t)(m0+8)*GN + n) = a1;
            }
        }
    }
}

__global__ __launch_bounds__(256, 3)
void gemm_qkv(const __half* __restrict__ Xh, const __half* __restrict__ Xl,
              const __half* __restrict__ Wqh, const __half* __restrict__ Wkh,
              const __half* __restrict__ Wvh,
              __half* __restrict__ Qh, __half* __restrict__ Ql,
              __half* __restrict__ Kh, __half* __restrict__ Vh,
              __half* __restrict__ LoSink)
{
    extern __shared__ char smem[];
    const int cRow = blockIdx.y << 6;
    const int cCol = blockIdx.x << 7;
    const int z = blockIdx.z;
    const __half* Bh;
    __half *Chi, *Clo;
    float alpha;
    if (z == 0)      { Bh = Wqh; Chi = Qh; Clo = Ql;     alpha = 0.125f; }
    else if (z == 1) { Bh = Wkh; Chi = Kh; Clo = LoSink; alpha = 1.0f; }
    else             { Bh = Wvh; Chi = Vh; Clo = LoSink; alpha = 1.0f; }
    gemm64_core<true>(Xh, Xl, Bh, nullptr, Chi, Clo, alpha, cRow, cCol, smem);
}

__global__ __launch_bounds__(256, 3)
void gemm_out(const __half* __restrict__ AOh, const __half* __restrict__ AOl,
              const __half* __restrict__ Woh, float* __restrict__ out)
{
    extern __shared__ char smem[];
    gemm64_core<false>(AOh, AOl, Woh, out, nullptr, nullptr, 1.0f,
                       blockIdx.y << 6, blockIdx.x << 7, smem);
}

// ---------------------------------------------------------------------------
// Flash attention, causal, 2-pass f16: S=(Qh+Ql)Kh, O=(Ph+Pl)Vh.
// 64-row q-tiles, 128 threads (4 warps x 16 rows), 3-stage KV, 3 CTAs/SM.
// ---------------------------------------------------------------------------
#define FQSTR 72
#define FTILE (64*FQSTR*2)                 /* 9216 per 64x64 tile */
#define FSTAGE (2*FTILE)                   /* Kh,Vh = 18432 */
#define FLASH_SMEM (2*FTILE + 3*FSTAGE)    /* Qh,Ql + 3 stages = 73728 */

__global__ __launch_bounds__(128, 3)
void flash_mma(const __half* __restrict__ Qh_, const __half* __restrict__ Ql_,
               const __half* __restrict__ Kh_, const __half* __restrict__ Vh_,
               __half* __restrict__ AOh, __half* __restrict__ AOl)
{
    extern __shared__ char smc[];
    const int qt  = (int)gridDim.x - 1 - (int)blockIdx.x;  // heavy first
    const int h   = blockIdx.y, b = blockIdx.z;
    const int tid = threadIdx.x;
    const int lane = tid & 31, w = tid >> 5;               // 4 warps
    const int qbase = qt*64;
    const int ktmax = qt;

    const uint32_t sb  = smem_u32(smc);
    const uint32_t uQh = sb;
    const uint32_t uQl = sb + FTILE;
    const uint32_t uKV = sb + 2*FTILE;

    const __half* qsrc[2]  = {Qh_, Ql_};
    const __half* kvsrc[2] = {Kh_, Vh_};
    const size_t hofs = (size_t)h*64;

    auto load_kv = [&](int kt, int s) {
#pragma unroll
        for (int i = 0; i < 8; i++) {
            int id = tid + i*128;
            int a = id >> 9, r = (id >> 3) & 63, c = id & 7;
            const __half* g = kvsrc[a] + (size_t)(b*SS + kt*64 + r)*DD + hofs + c*8;
            cp_async16(uKV + s*FSTAGE + a*FTILE + (uint32_t)(r*FQSTR + c*8)*2, g);
        }
    };

#pragma unroll
    for (int i = 0; i < 8; i++) {
        int id = tid + i*128;
        int a = id >> 9, r = (id >> 3) & 63, c = id & 7;
        const __half* g = qsrc[a] + (size_t)(b*SS + qbase + r)*DD + hofs + c*8;
        cp_async16((a ? uQl : uQh) + (uint32_t)(r*FQSTR + c*8)*2, g);
    }
    load_kv(0, 0);
    cp_commit();
    if (ktmax >= 1) { load_kv(1, 1); cp_commit(); }

    const int gid = lane >> 2, tig = lane & 3;
    const int qrow_off = ((lane>>3)&1)*8 + (lane&7);
    const int qd_off   = (lane>>4)*8;
    const int krow_off = (lane>>4)*8 + (lane&7);
    const int kd_off   = ((lane>>3)&1)*8;
    const int vrow_off = ((lane>>3)&1)*8 + (lane&7);
    const int vd_off   = (lane>>4)*8;

    uint32_t qh[4][4], ql[4][4];

    float m0 = -INFINITY, m1 = -INFINITY, l0 = 0.f, l1 = 0.f;
    float oacc[8][4];
#pragma unroll
    for (int nt = 0; nt < 8; nt++)
#pragma unroll
        for (int q = 0; q < 4; q++) oacc[nt][q] = 0.f;

    const int row0 = qbase + 16*w + gid;
    const int row1 = row0 + 8;

    for (int kt = 0; kt <= ktmax; kt++) {
        if (kt + 2 <= ktmax) { load_kv(kt + 2, (kt + 2) % 3); cp_commit(); }
        if (kt + 2 <= ktmax)      cp_wait<2>();
        else if (kt + 1 <= ktmax) cp_wait<1>();
        else                      cp_wait<0>();
        __syncthreads();

        if (kt == 0) {
            uint32_t ah = uQh + (uint32_t)((16*w + qrow_off)*FQSTR + qd_off)*2;
            uint32_t al = uQl + (uint32_t)((16*w + qrow_off)*FQSTR + qd_off)*2;
#pragma unroll
            for (int kk = 0; kk < 4; kk++) {
                ldm_x4(qh[kk], ah + kk*32);
                ldm_x4(ql[kk], al + kk*32);
            }
        }

        const uint32_t st = uKV + (uint32_t)(kt % 3)*FSTAGE;
        {
            float sacc[8][4];
#pragma unroll
            for (int nt = 0; nt < 8; nt++)
#pragma unroll
                for (int q = 0; q < 4; q++) sacc[nt][q] = 0.f;

            // ---- S = (Qh + Ql) * Kh ----
#pragma unroll
            for (int kk = 0; kk < 4; kk++) {
                const uint32_t kb0 = st + (uint32_t)(krow_off*FQSTR + kd_off + 16*kk)*2;
                uint32_t kb[8][2];
#pragma unroll
                for (int p = 0; p < 4; p++) {
                    uint32_t r[4];
                    ldm_x4(r, kb0 + (uint32_t)(16*p*FQSTR)*2);
                    kb[2*p][0] = r[0]; kb[2*p][1] = r[1];
                    kb[2*p+1][0] = r[2]; kb[2*p+1][1] = r[3];
                }
#pragma unroll
                for (int nt = 0; nt < 8; nt++) {
                    mma_f32acc(sacc[nt], qh[kk], kb[nt]);
                    mma_f32acc(sacc[nt], ql[kk], kb[nt]);
                }
            }

            // ---- causal mask (diagonal tile only) ----
            if (kt == qt) {
                const int colb = kt*64 + 2*tig;
#pragma unroll
                for (int nt = 0; nt < 8; nt++) {
                    int c0 = colb + 8*nt, c1 = c0 + 1;
                    if (c0 > row0) sacc[nt][0] = -1e10f;
                    if (c1 > row0) sacc[nt][1] = -1e10f;
                    if (c0 > row1) sacc[nt][2] = -1e10f;
                    if (c1 > row1) sacc[nt][3] = -1e10f;
                }
            }

            // ---- online softmax ----
            float rm0 = -INFINITY, rm1 = -INFINITY;
#pragma unroll
            for (int nt = 0; nt < 8; nt++) {
                rm0 = fmaxf(rm0, fmaxf(sacc[nt][0], sacc[nt][1]));
                rm1 = fmaxf(rm1, fmaxf(sacc[nt][2], sacc[nt][3]));
            }
            rm0 = warp_rmax(rm0); rm1 = warp_rmax(rm1);
            float mn0 = fmaxf(m0, rm0), mn1 = fmaxf(m1, rm1);
            float cr0 = __expf(m0 - mn0), cr1 = __expf(m1 - mn1);
            m0 = mn0; m1 = mn1;
            float ps0 = 0.f, ps1 = 0.f;
#pragma unroll
            for (int nt = 0; nt < 8; nt++) {
                float p0 = __expf(sacc[nt][0] - mn0);
                float p1 = __expf(sacc[nt][1] - mn0);
                float p2 = __expf(sacc[nt][2] - mn1);
                float p3 = __expf(sacc[nt][3] - mn1);
                sacc[nt][0] = p0; sacc[nt][1] = p1; sacc[nt][2] = p2; sacc[nt][3] = p3;
                ps0 += p0 + p1; ps1 += p2 + p3;
            }
            ps0 = warp_rsum(ps0); ps1 = warp_rsum(ps1);
            l0 = l0*cr0 + ps0; l1 = l1*cr1 + ps1;
#pragma unroll
            for (int nt = 0; nt < 8; nt++) {
                oacc[nt][0] *= cr0; oacc[nt][1] *= cr0;
                oacc[nt][2] *= cr1; oacc[nt][3] *= cr1;
            }

            // ---- O += (Ph + Pl) * Vh ----
#pragma unroll
            for (int kk = 0; kk < 4; kk++) {
                uint32_t pah[4], pal[4];
#pragma unroll
                for (int jj = 0; jj < 2; jj++) {
                    const float* s4 = sacc[2*kk + jj];
                    uint32_t h01 = packh2(s4[0], s4[1]);
                    uint32_t h23 = packh2(s4[2], s4[3]);
                    float2 f01 = unpackh2(h01), f23 = unpackh2(h23);
                    pah[2*jj]   = h01;
                    pah[2*jj+1] = h23;
                    pal[2*jj]   = packh2(s4[0] - f01.x, s4[1] - f01.y);
                    pal[2*jj+1] = packh2(s4[2] - f23.x, s4[3] - f23.y);
                }
                const uint32_t vb0 = st + FTILE + (uint32_t)((16*kk + vrow_off)*FQSTR + vd_off)*2;
                uint32_t vb[8][2];
#pragma unroll
                for (int p = 0; p < 4; p++) {
                    uint32_t r[4];
                    ldm_x4_t(r, vb0 + (uint32_t)(16*p)*2);
                    vb[2*p][0] = r[0]; vb[2*p][1] = r[1];
                    vb[2*p+1][0] = r[2]; vb[2*p+1][1] = r[3];
                }
#pragma unroll
                for (int nt = 0; nt < 8; nt++) {
                    mma_f32acc(oacc[nt], pah, vb[nt]);
                    mma_f32acc(oacc[nt], pal, vb[nt]);
                }
            }
        }
        __syncthreads();
    }

    // ---- epilogue: normalize + split to f16 hi/lo ----
    const float inv0 = 1.f / l0, inv1 = 1.f / l1;
    const size_t r0g = (size_t)(b*SS + row0);
    const size_t r1g = (size_t)(b*SS + row1);
#pragma unroll
    for (int nt = 0; nt < 8; nt++) {
        const size_t col = hofs + 8*nt + 2*tig;
        float x0 = oacc[nt][0]*inv0, x1 = oacc[nt][1]*inv0;
        float x2 = oacc[nt][2]*inv1, x3 = oacc[nt][3]*inv1;
        uint32_t h01 = packh2(x0, x1), h23 = packh2(x2, x3);
        float2 f01 = unpackh2(h01), f23 = unpackh2(h23);
        uint32_t l01 = packh2(x0 - f01.x, x1 - f01.y);
        uint32_t l23 = packh2(x2 - f23.x, x3 - f23.y);
        *(uint32_t*)(AOh + r0g*DD + col) = h01;
        *(uint32_t*)(AOl + r0g*DD + col) = l01;
        *(uint32_t*)(AOh + r1g*DD + col) = h23;
        *(uint32_t*)(AOl + r1g*DD + col) = l23;
    }
}

// ---------------------------------------------------------------------------
extern "C" void kernel_launch(void* const* d_in, const int* in_sizes, int n_in,
                              void* d_out, int out_size)
{
    (void)in_sizes; (void)n_in; (void)out_size;
    const float* X  = (const float*)d_in[0];
    const float* Wq = (const float*)d_in[1];
    const float* Wk = (const float*)d_in[2];
    const float* Wv = (const float*)d_in[3];
    const float* Wo = (const float*)d_in[4];
    float* out = (float*)d_out;

    __half *Xh, *Xl, *Qh, *Ql, *Kh, *Vh, *AOh, *AOl, *LoSink;
    __half *Wqh, *Wkh, *Wvh, *Woh;
    cudaGetSymbolAddress((void**)&Xh,  g_Xh);
    cudaGetSymbolAddress((void**)&Xl,  g_Xl);
    cudaGetSymbolAddress((void**)&Qh,  g_Qh);
    cudaGetSymbolAddress((void**)&Ql,  g_Ql);
    cudaGetSymbolAddress((void**)&Kh,  g_Kh);
    cudaGetSymbolAddress((void**)&Vh,  g_Vh);
    cudaGetSymbolAddress((void**)&AOh, g_AOh);
    cudaGetSymbolAddress((void**)&AOl, g_AOl);
    cudaGetSymbolAddress((void**)&LoSink, g_LoSink);
    cudaGetSymbolAddress((void**)&Wqh, g_Wqh);
    cudaGetSymbolAddress((void**)&Wkh, g_Wkh);
    cudaGetSymbolAddress((void**)&Wvh, g_Wvh);
    cudaGetSymbolAddress((void**)&Woh, g_Woh);

    cudaFuncSetAttribute(gemm_qkv, cudaFuncAttributeMaxDynamicSharedMemorySize, GEMM_SMEM);
    cudaFuncSetAttribute(gemm_out, cudaFuncAttributeMaxDynamicSharedMemorySize, GEMM_SMEM);
    cudaFuncSetAttribute(flash_mma, cudaFuncAttributeMaxDynamicSharedMemorySize, FLASH_SMEM);

    // launches 1-5 (ncu -s 5 window lands on gemm_qkv)
    split_f16<<<512, 256>>>(X, Xh, Xl, GM*DD/4);
    conv_f16<<<256, 256>>>(Wq, Wqh, DD*DD/4);
    conv_f16<<<256, 256>>>(Wk, Wkh, DD*DD/4);
    conv_f16<<<256, 256>>>(Wv, Wvh, DD*DD/4);
    conv_f16<<<256, 256>>>(Wo, Woh, DD*DD/4);

    // launch 6: fused Q/K/V projections (3 CTAs/SM)
    gemm_qkv<<<dim3(GN/128, GM/64, 3), 256, GEMM_SMEM>>>(
        Xh, Xl, Wqh, Wkh, Wvh, Qh, Ql, Kh, Vh, LoSink);

    // launch 7: flash attention (64-row tiles, 3 CTAs/SM)
    flash_mma<<<dim3(SS/64, HH, BB), 128, FLASH_SMEM>>>(Qh, Ql, Kh, Vh, AOh, AOl);

    // launch 8: output projection
    gemm_out<<<dim3(GN/128, GM/64, 1), 256, GEMM_SMEM>>>(AOh, AOl, Woh, out);
}

// round 15
// speedup vs baseline: 2.0365x; 1.1550x over previous
#include <cuda_runtime.h>
#include <cuda_fp16.h>
#include <math.h>
#include <stdint.h>

#define BB 2
#define SS 2048
#define DD 1024
#define HH 16
#define GM (BB*SS)   /* 4096 */
#define GN DD
#define GK DD

// ---------------- scratch (allocation-free) ----------------
__device__ __half g_Xh[GM*DD],  g_Xl[GM*DD];
__device__ __half g_Qh[GM*DD],  g_Ql[GM*DD];
__device__ __half g_Kh[GM*DD];
__device__ __half g_Vh[GM*DD];
__device__ __half g_AOh[GM*DD], g_AOl[GM*DD];
__device__ __half g_Wqh[DD*DD];
__device__ __half g_Wkh[DD*DD];
__device__ __half g_Wvh[DD*DD];
__device__ __half g_Woh[DD*DD];

// ---------------- helpers ----------------
__device__ __forceinline__ uint32_t smem_u32(const void* p) {
    return (uint32_t)__cvta_generic_to_shared(p);
}
__device__ __forceinline__ void cp_async16(uint32_t dst, const void* src) {
    asm volatile("cp.async.cg.shared.global [%0], [%1], 16;" :: "r"(dst), "l"(src) : "memory");
}
__device__ __forceinline__ void cp_commit() {
    asm volatile("cp.async.commit_group;" ::: "memory");
}
template<int N>
__device__ __forceinline__ void cp_wait() {
    asm volatile("cp.async.wait_group %0;" :: "n"(N) : "memory");
}
__device__ __forceinline__ void ldm_x4(uint32_t* r, uint32_t addr) {
    asm volatile("ldmatrix.sync.aligned.m8n8.x4.shared.b16 {%0,%1,%2,%3}, [%4];"
                 : "=r"(r[0]), "=r"(r[1]), "=r"(r[2]), "=r"(r[3]) : "r"(addr));
}
__device__ __forceinline__ void ldm_x4_t(uint32_t* r, uint32_t addr) {
    asm volatile("ldmatrix.sync.aligned.m8n8.x4.trans.shared.b16 {%0,%1,%2,%3}, [%4];"
                 : "=r"(r[0]), "=r"(r[1]), "=r"(r[2]), "=r"(r[3]) : "r"(addr));
}
__device__ __forceinline__ void mma_f32acc(float* c, const uint32_t* a, const uint32_t* b) {
    asm volatile("mma.sync.aligned.m16n8k16.row.col.f32.f16.f16.f32 "
                 "{%0,%1,%2,%3}, {%4,%5,%6,%7}, {%8,%9}, {%0,%1,%2,%3};"
                 : "+f"(c[0]), "+f"(c[1]), "+f"(c[2]), "+f"(c[3])
                 : "r"(a[0]), "r"(a[1]), "r"(a[2]), "r"(a[3]), "r"(b[0]), "r"(b[1]));
}
__device__ __forceinline__ uint32_t packh2(float a, float b) {
    __half2 h = __floats2half2_rn(a, b);
    return *(uint32_t*)&h;
}
__device__ __forceinline__ float2 unpackh2(uint32_t r) {
    __half2 h = *(__half2*)&r;
    return __half22float2(h);
}
__device__ __forceinline__ float warp_rmax(float x) {
    x = fmaxf(x, __shfl_xor_sync(0xffffffffu, x, 1));
    x = fmaxf(x, __shfl_xor_sync(0xffffffffu, x, 2));
    return x;
}
__device__ __forceinline__ float warp_rsum(float x) {
    x += __shfl_xor_sync(0xffffffffu, x, 1);
    x += __shfl_xor_sync(0xffffffffu, x, 2);
    return x;
}

// ---------------- fused conversions: X split + 4 weight hi-convs ----------------
#define NX4 (GM*DD/4)     /* 1048576 */
#define NW4 (DD*DD/4)     /* 262144  */
__global__ void convert_all(const float* __restrict__ X,
                            const float* __restrict__ Wq, const float* __restrict__ Wk,
                            const float* __restrict__ Wv, const float* __restrict__ Wo,
                            __half* __restrict__ Xh, __half* __restrict__ Xl,
                            __half* __restrict__ Wqh, __half* __restrict__ Wkh,
                            __half* __restrict__ Wvh, __half* __restrict__ Woh)
{
    int i = blockIdx.x*blockDim.x + threadIdx.x;
    const int stride = gridDim.x*blockDim.x;
    const int total = NX4 + 4*NW4;
    for (; i < total; i += stride) {
        if (i < NX4) {
            float4 v = ((const float4*)X)[i];
            uint32_t h01 = packh2(v.x, v.y), h23 = packh2(v.z, v.w);
            float2 f01 = unpackh2(h01), f23 = unpackh2(h23);
            ((uint32_t*)Xh)[i*2]   = h01;
            ((uint32_t*)Xh)[i*2+1] = h23;
            ((uint32_t*)Xl)[i*2]   = packh2(v.x - f01.x, v.y - f01.y);
            ((uint32_t*)Xl)[i*2+1] = packh2(v.z - f23.x, v.w - f23.y);
        } else {
            int r = i - NX4;
            int w = r >> 18;           // NW4 = 2^18
            int j = r & (NW4 - 1);
            const float* src = (w == 0) ? Wq : (w == 1) ? Wk : (w == 2) ? Wv : Wo;
            __half* dst = (w == 0) ? Wqh : (w == 1) ? Wkh : (w == 2) ? Wvh : Woh;
            float4 v = ((const float4*)src)[j];
            ((uint32_t*)dst)[j*2]   = packh2(v.x, v.y);
            ((uint32_t*)dst)[j*2+1] = packh2(v.z, v.w);
        }
    }
}

// ---------------- f16 GEMM core, tile 64x128, runtime npass/omode ----------------
// Stage = Ah(9216) + Al(9216) + Bh(18432) = 36864; 2-stage = 73728 -> 3 CTAs/SM.
#define KCH 64
#define NCH (GK/KCH)
#define SRE 72
#define SRB (SRE*2)
#define AT_B (64*SRB)               /* 9216  */
#define BT_B (128*SRB)              /* 18432 */
#define OFF_AH 0
#define OFF_AL (AT_B)
#define OFF_BH (2*AT_B)
#define STAGE64 (2*AT_B + BT_B)     /* 36864 */
#define GEMM_SMEM (2*STAGE64)       /* 73728 */

// omode: 0 = fp32 out (Cf), 1 = split hi/lo out, 2 = hi-only out
__device__ __forceinline__ void gemm64_core(
    const __half* __restrict__ Ah, const __half* __restrict__ Al,
    const __half* __restrict__ Bh,
    float* __restrict__ Cf, __half* __restrict__ Chi, __half* __restrict__ Clo,
    float alpha, int cRow, int cCol, char* smem, int npass, int omode)
{
    const uint32_t sb = smem_u32(smem);
    const int tid  = threadIdx.x;
    const int lane = tid & 31;
    const int warp = tid >> 5;
    const int wm   = warp & 1;
    const int wn   = warp >> 1;

    const int lr = tid >> 3;
    const int lc = tid & 7;

    const uint32_t aOff = (uint32_t)((lane & 15)*SRB + (lane >> 4)*16 + wm*32*SRB);
    const uint32_t bOff = (uint32_t)(((lane & 7) + ((lane >> 4) << 3))*SRB
                                     + ((lane >> 3) & 1)*16 + wn*32*SRB);

    float acc[2][4][4];
#pragma unroll
    for (int mt = 0; mt < 2; mt++)
#pragma unroll
        for (int nt = 0; nt < 4; nt++)
#pragma unroll
            for (int q = 0; q < 4; q++) acc[mt][nt][q] = 0.f;

    auto issue_chunk = [&](int j, int s) {
        const uint32_t st = sb + (uint32_t)s*STAGE64;
        const int k0 = j*KCH;
#pragma unroll
        for (int r = 0; r < 2; r++)
            cp_async16(st + OFF_AH + (lr + 32*r)*SRB + lc*16,
                       Ah + (size_t)(cRow + lr + 32*r)*GK + k0 + lc*8);
        if (npass == 2) {
#pragma unroll
            for (int r = 0; r < 2; r++)
                cp_async16(st + OFF_AL + (lr + 32*r)*SRB + lc*16,
                           Al + (size_t)(cRow + lr + 32*r)*GK + k0 + lc*8);
        }
#pragma unroll
        for (int r = 0; r < 4; r++)
            cp_async16(st + OFF_BH + (lr + 32*r)*SRB + lc*16,
                       Bh + (size_t)(cCol + lr + 32*r)*GK + k0 + lc*8);
        cp_commit();
    };

    issue_chunk(0, 0);

    for (int j = 0; j < NCH; j++) {
        if (j + 1 < NCH) { issue_chunk(j + 1, (j + 1) & 1); cp_wait<1>(); }
        else             { cp_wait<0>(); }
        __syncthreads();

        const uint32_t stg = sb + (uint32_t)(j & 1)*STAGE64;
        const uint32_t aBH = stg + OFF_AH + aOff;
        const uint32_t aBL = stg + OFF_AL + aOff;
        const uint32_t bBH = stg + OFF_BH + bOff;
#pragma unroll
        for (int k16 = 0; k16 < 4; k16++) {
            uint32_t ah2[2][4], bh2[2][4];
            ldm_x4(ah2[0], aBH + k16*32);
            ldm_x4(ah2[1], aBH + k16*32 + 16*SRB);
            ldm_x4(bh2[0], bBH + k16*32);
            ldm_x4(bh2[1], bBH + k16*32 + 16*SRB);
#pragma unroll
            for (int mt = 0; mt < 2; mt++)
#pragma unroll
                for (int ng = 0; ng < 2; ng++) {
                    mma_f32acc(acc[mt][2*ng+0], ah2[mt], &bh2[ng][0]);
                    mma_f32acc(acc[mt][2*ng+1], ah2[mt], &bh2[ng][2]);
                }
            if (npass == 2) {
                uint32_t al2[2][4];
                ldm_x4(al2[0], aBL + k16*32);
                ldm_x4(al2[1], aBL + k16*32 + 16*SRB);
#pragma unroll
                for (int mt = 0; mt < 2; mt++)
#pragma unroll
                    for (int ng = 0; ng < 2; ng++) {
                        mma_f32acc(acc[mt][2*ng+0], al2[mt], &bh2[ng][0]);
                        mma_f32acc(acc[mt][2*ng+1], al2[mt], &bh2[ng][2]);
                    }
            }
        }
        __syncthreads();
    }

    const int gid = lane >> 2, tig = lane & 3;
#pragma unroll
    for (int mt = 0; mt < 2; mt++) {
        const int m0 = cRow + wm*32 + mt*16 + gid;
#pragma unroll
        for (int nt = 0; nt < 4; nt++) {
            const int n = cCol + wn*32 + nt*8 + tig*2;
            float v0 = acc[mt][nt][0]*alpha, v1 = acc[mt][nt][1]*alpha;
            float v2 = acc[mt][nt][2]*alpha, v3 = acc[mt][nt][3]*alpha;
            if (omode == 0) {
                float2 a0 = {v0, v1}, a1 = {v2, v3};
                *(float2*)(Cf + (size_t)m0*GN + n)     = a0;
                *(float2*)(Cf + (size_t)(m0+8)*GN + n) = a1;
            } else {
                uint32_t h01 = packh2(v0, v1), h23 = packh2(v2, v3);
                *(uint32_t*)(Chi + (size_t)m0*GN + n)     = h01;
                *(uint32_t*)(Chi + (size_t)(m0+8)*GN + n) = h23;
                if (omode == 1) {
                    float2 f01 = unpackh2(h01), f23 = unpackh2(h23);
                    *(uint32_t*)(Clo + (size_t)m0*GN + n) =
                        packh2(v0 - f01.x, v1 - f01.y);
                    *(uint32_t*)(Clo + (size_t)(m0+8)*GN + n) =
                        packh2(v2 - f23.x, v3 - f23.y);
                }
            }
        }
    }
}

// Fused Q/K/V projection. z=0: Q (2-pass, split out); z=1: K, z=2: V (1-pass, hi out).
__global__ __launch_bounds__(256, 3)
void gemm_qkv(const __half* __restrict__ Xh, const __half* __restrict__ Xl,
              const __half* __restrict__ Wqh, const __half* __restrict__ Wkh,
              const __half* __restrict__ Wvh,
              __half* __restrict__ Qh, __half* __restrict__ Ql,
              __half* __restrict__ Kh, __half* __restrict__ Vh)
{
    extern __shared__ char smem[];
    const int cRow = blockIdx.y << 6;
    const int cCol = blockIdx.x << 7;
    const int z = blockIdx.z;
    const __half* Bh;
    __half *Chi, *Clo;
    float alpha;
    int npass, omode;
    if (z == 0)      { Bh = Wqh; Chi = Qh; Clo = Ql;      alpha = 0.125f; npass = 2; omode = 1; }
    else if (z == 1) { Bh = Wkh; Chi = Kh; Clo = nullptr; alpha = 1.0f;   npass = 1; omode = 2; }
    else             { Bh = Wvh; Chi = Vh; Clo = nullptr; alpha = 1.0f;   npass = 1; omode = 2; }
    gemm64_core(Xh, Xl, Bh, nullptr, Chi, Clo, alpha, cRow, cCol, smem, npass, omode);
}

__global__ __launch_bounds__(256, 3)
void gemm_out(const __half* __restrict__ AOh, const __half* __restrict__ AOl,
              const __half* __restrict__ Woh, float* __restrict__ out)
{
    extern __shared__ char smem[];
    gemm64_core(AOh, AOl, Woh, out, nullptr, nullptr, 1.0f,
                blockIdx.y << 6, blockIdx.x << 7, smem, 2, 0);
}

// ---------------------------------------------------------------------------
// Flash attention, causal, 2-pass f16: S=(Qh+Ql)Kh, O=(Ph+Pl)Vh.
// 64-row q-tiles, 128 threads, 3-stage KV, 3 CTAs/SM. (R14 winning version.)
// ---------------------------------------------------------------------------
#define FQSTR 72
#define FTILE (64*FQSTR*2)
#define FSTAGE (2*FTILE)
#define FLASH_SMEM (2*FTILE + 3*FSTAGE)    /* 73728 */

__global__ __launch_bounds__(128, 3)
void flash_mma(const __half* __restrict__ Qh_, const __half* __restrict__ Ql_,
               const __half* __restrict__ Kh_, const __half* __restrict__ Vh_,
               __half* __restrict__ AOh, __half* __restrict__ AOl)
{
    extern __shared__ char smc[];
    const int qt  = (int)gridDim.x - 1 - (int)blockIdx.x;
    const int h   = blockIdx.y, b = blockIdx.z;
    const int tid = threadIdx.x;
    const int lane = tid & 31, w = tid >> 5;
    const int qbase = qt*64;
    const int ktmax = qt;

    const uint32_t sb  = smem_u32(smc);
    const uint32_t uQh = sb;
    const uint32_t uQl = sb + FTILE;
    const uint32_t uKV = sb + 2*FTILE;

    const __half* qsrc[2]  = {Qh_, Ql_};
    const __half* kvsrc[2] = {Kh_, Vh_};
    const size_t hofs = (size_t)h*64;

    auto load_kv = [&](int kt, int s) {
#pragma unroll
        for (int i = 0; i < 8; i++) {
            int id = tid + i*128;
            int a = id >> 9, r = (id >> 3) & 63, c = id & 7;
            const __half* g = kvsrc[a] + (size_t)(b*SS + kt*64 + r)*DD + hofs + c*8;
            cp_async16(uKV + s*FSTAGE + a*FTILE + (uint32_t)(r*FQSTR + c*8)*2, g);
        }
    };

#pragma unroll
    for (int i = 0; i < 8; i++) {
        int id = tid + i*128;
        int a = id >> 9, r = (id >> 3) & 63, c = id & 7;
        const __half* g = qsrc[a] + (size_t)(b*SS + qbase + r)*DD + hofs + c*8;
        cp_async16((a ? uQl : uQh) + (uint32_t)(r*FQSTR + c*8)*2, g);
    }
    load_kv(0, 0);
    cp_commit();
    if (ktmax >= 1) { load_kv(1, 1); cp_commit(); }

    const int gid = lane >> 2, tig = lane & 3;
    const int qrow_off = ((lane>>3)&1)*8 + (lane&7);
    const int qd_off   = (lane>>4)*8;
    const int krow_off = (lane>>4)*8 + (lane&7);
    const int kd_off   = ((lane>>3)&1)*8;
    const int vrow_off = ((lane>>3)&1)*8 + (lane&7);
    const int vd_off   = (lane>>4)*8;

    uint32_t qh[4][4], ql[4][4];

    float m0 = -INFINITY, m1 = -INFINITY, l0 = 0.f, l1 = 0.f;
    float oacc[8][4];
#pragma unroll
    for (int nt = 0; nt < 8; nt++)
#pragma unroll
        for (int q = 0; q < 4; q++) oacc[nt][q] = 0.f;

    const int row0 = qbase + 16*w + gid;
    const int row1 = row0 + 8;

    for (int kt = 0; kt <= ktmax; kt++) {
        if (kt + 2 <= ktmax) { load_kv(kt + 2, (kt + 2) % 3); cp_commit(); }
        if (kt + 2 <= ktmax)      cp_wait<2>();
        else if (kt + 1 <= ktmax) cp_wait<1>();
        else                      cp_wait<0>();
        __syncthreads();

        if (kt == 0) {
            uint32_t ah = uQh + (uint32_t)((16*w + qrow_off)*FQSTR + qd_off)*2;
            uint32_t al = uQl + (uint32_t)((16*w + qrow_off)*FQSTR + qd_off)*2;
#pragma unroll
            for (int kk = 0; kk < 4; kk++) {
                ldm_x4(qh[kk], ah + kk*32);
                ldm_x4(ql[kk], al + kk*32);
            }
        }

        const uint32_t st = uKV + (uint32_t)(kt % 3)*FSTAGE;
        {
            float sacc[8][4];
#pragma unroll
            for (int nt = 0; nt < 8; nt++)
#pragma unroll
                for (int q = 0; q < 4; q++) sacc[nt][q] = 0.f;

#pragma unroll
            for (int kk = 0; kk < 4; kk++) {
                const uint32_t kb0 = st + (uint32_t)(krow_off*FQSTR + kd_off + 16*kk)*2;
                uint32_t kb[8][2];
#pragma unroll
                for (int p = 0; p < 4; p++) {
                    uint32_t r[4];
                    ldm_x4(r, kb0 + (uint32_t)(16*p*FQSTR)*2);
                    kb[2*p][0] = r[0]; kb[2*p][1] = r[1];
                    kb[2*p+1][0] = r[2]; kb[2*p+1][1] = r[3];
                }
#pragma unroll
                for (int nt = 0; nt < 8; nt++) {
                    mma_f32acc(sacc[nt], qh[kk], kb[nt]);
                    mma_f32acc(sacc[nt], ql[kk], kb[nt]);
                }
            }

            if (kt == qt) {
                const int colb = kt*64 + 2*tig;
#pragma unroll
                for (int nt = 0; nt < 8; nt++) {
                    int c0 = colb + 8*nt, c1 = c0 + 1;
                    if (c0 > row0) sacc[nt][0] = -1e10f;
                    if (c1 > row0) sacc[nt][1] = -1e10f;
                    if (c0 > row1) sacc[nt][2] = -1e10f;
                    if (c1 > row1) sacc[nt][3] = -1e10f;
                }
            }

            float rm0 = -INFINITY, rm1 = -INFINITY;
#pragma unroll
            for (int nt = 0; nt < 8; nt++) {
                rm0 = fmaxf(rm0, fmaxf(sacc[nt][0], sacc[nt][1]));
                rm1 = fmaxf(rm1, fmaxf(sacc[nt][2], sacc[nt][3]));
            }
            rm0 = warp_rmax(rm0); rm1 = warp_rmax(rm1);
            float mn0 = fmaxf(m0, rm0), mn1 = fmaxf(m1, rm1);
            float cr0 = __expf(m0 - mn0), cr1 = __expf(m1 - mn1);
            m0 = mn0; m1 = mn1;
            float ps0 = 0.f, ps1 = 0.f;
#pragma unroll
            for (int nt = 0; nt < 8; nt++) {
                float p0 = __expf(sacc[nt][0] - mn0);
                float p1 = __expf(sacc[nt][1] - mn0);
                float p2 = __expf(sacc[nt][2] - mn1);
                float p3 = __expf(sacc[nt][3] - mn1);
                sacc[nt][0] = p0; sacc[nt][1] = p1; sacc[nt][2] = p2; sacc[nt][3] = p3;
                ps0 += p0 + p1; ps1 += p2 + p3;
            }
            ps0 = warp_rsum(ps0); ps1 = warp_rsum(ps1);
            l0 = l0*cr0 + ps0; l1 = l1*cr1 + ps1;
#pragma unroll
            for (int nt = 0; nt < 8; nt++) {
                oacc[nt][0] *= cr0; oacc[nt][1] *= cr0;
                oacc[nt][2] *= cr1; oacc[nt][3] *= cr1;
            }

#pragma unroll
            for (int kk = 0; kk < 4; kk++) {
                uint32_t pah[4], pal[4];
#pragma unroll
                for (int jj = 0; jj < 2; jj++) {
                    const float* s4 = sacc[2*kk + jj];
                    uint32_t h01 = packh2(s4[0], s4[1]);
                    uint32_t h23 = packh2(s4[2], s4[3]);
                    float2 f01 = unpackh2(h01), f23 = unpackh2(h23);
                    pah[2*jj]   = h01;
                    pah[2*jj+1] = h23;
                    pal[2*jj]   = packh2(s4[0] - f01.x, s4[1] - f01.y);
                    pal[2*jj+1] = packh2(s4[2] - f23.x, s4[3] - f23.y);
                }
                const uint32_t vb0 = st + FTILE + (uint32_t)((16*kk + vrow_off)*FQSTR + vd_off)*2;
                uint32_t vb[8][2];
#pragma unroll
                for (int p = 0; p < 4; p++) {
                    uint32_t r[4];
                    ldm_x4_t(r, vb0 + (uint32_t)(16*p)*2);
                    vb[2*p][0] = r[0]; vb[2*p][1] = r[1];
                    vb[2*p+1][0] = r[2]; vb[2*p+1][1] = r[3];
                }
#pragma unroll
                for (int nt = 0; nt < 8; nt++) {
                    mma_f32acc(oacc[nt], pah, vb[nt]);
                    mma_f32acc(oacc[nt], pal, vb[nt]);
                }
            }
        }
        __syncthreads();
    }

    const float inv0 = 1.f / l0, inv1 = 1.f / l1;
    const size_t r0g = (size_t)(b*SS + row0);
    const size_t r1g = (size_t)(b*SS + row1);
#pragma unroll
    for (int nt = 0; nt < 8; nt++) {
        const size_t col = hofs + 8*nt + 2*tig;
        float x0 = oacc[nt][0]*inv0, x1 = oacc[nt][1]*inv0;
        float x2 = oacc[nt][2]*inv1, x3 = oacc[nt][3]*inv1;
        uint32_t h01 = packh2(x0, x1), h23 = packh2(x2, x3);
        float2 f01 = unpackh2(h01), f23 = unpackh2(h23);
        uint32_t l01 = packh2(x0 - f01.x, x1 - f01.y);
        uint32_t l23 = packh2(x2 - f23.x, x3 - f23.y);
        *(uint32_t*)(AOh + r0g*DD + col) = h01;
        *(uint32_t*)(AOl + r0g*DD + col) = l01;
        *(uint32_t*)(AOh + r1g*DD + col) = h23;
        *(uint32_t*)(AOl + r1g*DD + col) = l23;
    }
}

// ---------------------------------------------------------------------------
extern "C" void kernel_launch(void* const* d_in, const int* in_sizes, int n_in,
                              void* d_out, int out_size)
{
    (void)in_sizes; (void)n_in; (void)out_size;
    const float* X  = (const float*)d_in[0];
    const float* Wq = (const float*)d_in[1];
    const float* Wk = (const float*)d_in[2];
    const float* Wv = (const float*)d_in[3];
    const float* Wo = (const float*)d_in[4];
    float* out = (float*)d_out;

    __half *Xh, *Xl, *Qh, *Ql, *Kh, *Vh, *AOh, *AOl;
    __half *Wqh, *Wkh, *Wvh, *Woh;
    cudaGetSymbolAddress((void**)&Xh,  g_Xh);
    cudaGetSymbolAddress((void**)&Xl,  g_Xl);
    cudaGetSymbolAddress((void**)&Qh,  g_Qh);
    cudaGetSymbolAddress((void**)&Ql,  g_Ql);
    cudaGetSymbolAddress((void**)&Kh,  g_Kh);
    cudaGetSymbolAddress((void**)&Vh,  g_Vh);
    cudaGetSymbolAddress((void**)&AOh, g_AOh);
    cudaGetSymbolAddress((void**)&AOl, g_AOl);
    cudaGetSymbolAddress((void**)&Wqh, g_Wqh);
    cudaGetSymbolAddress((void**)&Wkh, g_Wkh);
    cudaGetSymbolAddress((void**)&Wvh, g_Wvh);
    cudaGetSymbolAddress((void**)&Woh, g_Woh);

    cudaFuncSetAttribute(gemm_qkv, cudaFuncAttributeMaxDynamicSharedMemorySize, GEMM_SMEM);
    cudaFuncSetAttribute(gemm_out, cudaFuncAttributeMaxDynamicSharedMemorySize, GEMM_SMEM);
    cudaFuncSetAttribute(flash_mma, cudaFuncAttributeMaxDynamicSharedMemorySize, FLASH_SMEM);

    // launch 1: all conversions fused
    convert_all<<<2048, 256>>>(X, Wq, Wk, Wv, Wo, Xh, Xl, Wqh, Wkh, Wvh, Woh);

    // launch 2: fused Q/K/V projections (Q 2-pass; K,V 1-pass)
    gemm_qkv<<<dim3(GN/128, GM/64, 3), 256, GEMM_SMEM>>>(
        Xh, Xl, Wqh, Wkh, Wvh, Qh, Ql, Kh, Vh);

    // launch 3: flash attention
    flash_mma<<<dim3(SS/64, HH, BB), 128, FLASH_SMEM>>>(Qh, Ql, Kh, Vh, AOh, AOl);

    // launch 4: output projection (2-pass, fp32 out)
    gemm_out<<<dim3(GN/128, GM/64, 1), 256, GEMM_SMEM>>>(AOh, AOl, Woh, out);
}

// round 17
// speedup vs baseline: 2.1076x; 1.0349x over previous
#include <cuda_runtime.h>
#include <cuda_fp16.h>
#include <math.h>
#include <stdint.h>

#define BB 2
#define SS 2048
#define DD 1024
#define HH 16
#define GM (BB*SS)   /* 4096 */
#define GN DD
#define GK DD

// ---------------- scratch (allocation-free) ----------------
__device__ __half g_Xh[GM*DD],  g_Xl[GM*DD];
__device__ __half g_Qh[GM*DD];
__device__ __half g_Kh[GM*DD];
__device__ __half g_Vh[GM*DD];
__device__ __half g_AOh[GM*DD], g_AOl[GM*DD];
__device__ __half g_Wqh[DD*DD];
__device__ __half g_Wkh[DD*DD];
__device__ __half g_Wvh[DD*DD];
__device__ __half g_Woh[DD*DD];

// ---------------- helpers ----------------
__device__ __forceinline__ uint32_t smem_u32(const void* p) {
    return (uint32_t)__cvta_generic_to_shared(p);
}
__device__ __forceinline__ void cp_async16(uint32_t dst, const void* src) {
    asm volatile("cp.async.cg.shared.global [%0], [%1], 16;" :: "r"(dst), "l"(src) : "memory");
}
__device__ __forceinline__ void cp_commit() {
    asm volatile("cp.async.commit_group;" ::: "memory");
}
template<int N>
__device__ __forceinline__ void cp_wait() {
    asm volatile("cp.async.wait_group %0;" :: "n"(N) : "memory");
}
__device__ __forceinline__ void ldm_x4(uint32_t* r, uint32_t addr) {
    asm volatile("ldmatrix.sync.aligned.m8n8.x4.shared.b16 {%0,%1,%2,%3}, [%4];"
                 : "=r"(r[0]), "=r"(r[1]), "=r"(r[2]), "=r"(r[3]) : "r"(addr));
}
__device__ __forceinline__ void ldm_x4_t(uint32_t* r, uint32_t addr) {
    asm volatile("ldmatrix.sync.aligned.m8n8.x4.trans.shared.b16 {%0,%1,%2,%3}, [%4];"
                 : "=r"(r[0]), "=r"(r[1]), "=r"(r[2]), "=r"(r[3]) : "r"(addr));
}
__device__ __forceinline__ void mma_f32acc(float* c, const uint32_t* a, const uint32_t* b) {
    asm volatile("mma.sync.aligned.m16n8k16.row.col.f32.f16.f16.f32 "
                 "{%0,%1,%2,%3}, {%4,%5,%6,%7}, {%8,%9}, {%0,%1,%2,%3};"
                 : "+f"(c[0]), "+f"(c[1]), "+f"(c[2]), "+f"(c[3])
                 : "r"(a[0]), "r"(a[1]), "r"(a[2]), "r"(a[3]), "r"(b[0]), "r"(b[1]));
}
__device__ __forceinline__ uint32_t packh2(float a, float b) {
    __half2 h = __floats2half2_rn(a, b);
    return *(uint32_t*)&h;
}
__device__ __forceinline__ float2 unpackh2(uint32_t r) {
    __half2 h = *(__half2*)&r;
    return __half22float2(h);
}
__device__ __forceinline__ float warp_rmax(float x) {
    x = fmaxf(x, __shfl_xor_sync(0xffffffffu, x, 1));
    x = fmaxf(x, __shfl_xor_sync(0xffffffffu, x, 2));
    return x;
}
__device__ __forceinline__ float warp_rsum(float x) {
    x += __shfl_xor_sync(0xffffffffu, x, 1);
    x += __shfl_xor_sync(0xffffffffu, x, 2);
    return x;
}

// ---------------- fused conversions ----------------
#define NX4 (GM*DD/4)
#define NW4 (DD*DD/4)
__global__ void convert_all(const float* __restrict__ X,
                            const float* __restrict__ Wq, const float* __restrict__ Wk,
                            const float* __restrict__ Wv, const float* __restrict__ Wo,
                            __half* __restrict__ Xh, __half* __restrict__ Xl,
                            __half* __restrict__ Wqh, __half* __restrict__ Wkh,
                            __half* __restrict__ Wvh, __half* __restrict__ Woh)
{
    int i = blockIdx.x*blockDim.x + threadIdx.x;
    const int stride = gridDim.x*blockDim.x;
    const int total = NX4 + 4*NW4;
    for (; i < total; i += stride) {
        if (i < NX4) {
            float4 v = ((const float4*)X)[i];
            uint32_t h01 = packh2(v.x, v.y), h23 = packh2(v.z, v.w);
            float2 f01 = unpackh2(h01), f23 = unpackh2(h23);
            ((uint32_t*)Xh)[i*2]   = h01;
            ((uint32_t*)Xh)[i*2+1] = h23;
            ((uint32_t*)Xl)[i*2]   = packh2(v.x - f01.x, v.y - f01.y);
            ((uint32_t*)Xl)[i*2+1] = packh2(v.z - f23.x, v.w - f23.y);
        } else {
            int r = i - NX4;
            int w = r >> 18;
            int j = r & (NW4 - 1);
            const float* src = (w == 0) ? Wq : (w == 1) ? Wk : (w == 2) ? Wv : Wo;
            __half* dst = (w == 0) ? Wqh : (w == 1) ? Wkh : (w == 2) ? Wvh : Woh;
            float4 v = ((const float4*)src)[j];
            ((uint32_t*)dst)[j*2]   = packh2(v.x, v.y);
            ((uint32_t*)dst)[j*2+1] = packh2(v.z, v.w);
        }
    }
}

// ---------------- f16 GEMM core, tile 64x128, compile-time NPASS/OMODE ----------------
#define KCH 64
#define NCH (GK/KCH)
#define SRE 72
#define SRB (SRE*2)
#define AT_B (64*SRB)               /* 9216  */
#define BT_B (128*SRB)              /* 18432 */
// NPASS==2 layout: [Ah][Al][Bh]; NPASS==1: [Ah][Bh]
// OMODE: 0 = fp32 out, 1 = split hi/lo out, 2 = hi-only out

template<int NPASS, int OMODE>
__device__ __forceinline__ void gemm64_core(
    const __half* __restrict__ Ah, const __half* __restrict__ Al,
    const __half* __restrict__ Bh,
    float* __restrict__ Cf, __half* __restrict__ Chi, __half* __restrict__ Clo,
    float alpha, int cRow, int cCol, char* smem)
{
    constexpr uint32_t OFFB = (NPASS == 2) ? 2u*AT_B : (uint32_t)AT_B;
    constexpr uint32_t STG  = OFFB + BT_B;

    const uint32_t sb = smem_u32(smem);
    const int tid  = threadIdx.x;
    const int lane = tid & 31;
    const int warp = tid >> 5;
    const int wm   = warp & 1;
    const int wn   = warp >> 1;

    const int lr = tid >> 3;
    const int lc = tid & 7;

    const uint32_t aOff = (uint32_t)((lane & 15)*SRB + (lane >> 4)*16 + wm*32*SRB);
    const uint32_t bOff = (uint32_t)(((lane & 7) + ((lane >> 4) << 3))*SRB
                                     + ((lane >> 3) & 1)*16 + wn*32*SRB);

    float acc[2][4][4];
#pragma unroll
    for (int mt = 0; mt < 2; mt++)
#pragma unroll
        for (int nt = 0; nt < 4; nt++)
#pragma unroll
            for (int q = 0; q < 4; q++) acc[mt][nt][q] = 0.f;

    auto issue_chunk = [&](int j, int s) {
        const uint32_t st = sb + (uint32_t)s*STG;
        const int k0 = j*KCH;
#pragma unroll
        for (int r = 0; r < 2; r++)
            cp_async16(st + (lr + 32*r)*SRB + lc*16,
                       Ah + (size_t)(cRow + lr + 32*r)*GK + k0 + lc*8);
        if (NPASS == 2) {
#pragma unroll
            for (int r = 0; r < 2; r++)
                cp_async16(st + AT_B + (lr + 32*r)*SRB + lc*16,
                           Al + (size_t)(cRow + lr + 32*r)*GK + k0 + lc*8);
        }
#pragma unroll
        for (int r = 0; r < 4; r++)
            cp_async16(st + OFFB + (lr + 32*r)*SRB + lc*16,
                       Bh + (size_t)(cCol + lr + 32*r)*GK + k0 + lc*8);
        cp_commit();
    };

    issue_chunk(0, 0);

    for (int j = 0; j < NCH; j++) {
        if (j + 1 < NCH) { issue_chunk(j + 1, (j + 1) & 1); cp_wait<1>(); }
        else             { cp_wait<0>(); }
        __syncthreads();

        const uint32_t stg = sb + (uint32_t)(j & 1)*STG;
        const uint32_t aBH = stg + aOff;
        const uint32_t aBL = stg + AT_B + aOff;
        const uint32_t bBH = stg + OFFB + bOff;
#pragma unroll
        for (int k16 = 0; k16 < 4; k16++) {
            uint32_t ah2[2][4], bh2[2][4];
            ldm_x4(ah2[0], aBH + k16*32);
            ldm_x4(ah2[1], aBH + k16*32 + 16*SRB);
            ldm_x4(bh2[0], bBH + k16*32);
            ldm_x4(bh2[1], bBH + k16*32 + 16*SRB);
#pragma unroll
            for (int mt = 0; mt < 2; mt++)
#pragma unroll
                for (int ng = 0; ng < 2; ng++) {
                    mma_f32acc(acc[mt][2*ng+0], ah2[mt], &bh2[ng][0]);
                    mma_f32acc(acc[mt][2*ng+1], ah2[mt], &bh2[ng][2]);
                }
            if (NPASS == 2) {
                uint32_t al2[2][4];
                ldm_x4(al2[0], aBL + k16*32);
                ldm_x4(al2[1], aBL + k16*32 + 16*SRB);
#pragma unroll
                for (int mt = 0; mt < 2; mt++)
#pragma unroll
                    for (int ng = 0; ng < 2; ng++) {
                        mma_f32acc(acc[mt][2*ng+0], al2[mt], &bh2[ng][0]);
                        mma_f32acc(acc[mt][2*ng+1], al2[mt], &bh2[ng][2]);
                    }
            }
        }
        __syncthreads();
    }

    const int gid = lane >> 2, tig = lane & 3;
#pragma unroll
    for (int mt = 0; mt < 2; mt++) {
        const int m0 = cRow + wm*32 + mt*16 + gid;
#pragma unroll
        for (int nt = 0; nt < 4; nt++) {
            const int n = cCol + wn*32 + nt*8 + tig*2;
            float v0 = acc[mt][nt][0]*alpha, v1 = acc[mt][nt][1]*alpha;
            float v2 = acc[mt][nt][2]*alpha, v3 = acc[mt][nt][3]*alpha;
            if (OMODE == 0) {
                float2 a0 = {v0, v1}, a1 = {v2, v3};
                *(float2*)(Cf + (size_t)m0*GN + n)     = a0;
                *(float2*)(Cf + (size_t)(m0+8)*GN + n) = a1;
            } else {
                uint32_t h01 = packh2(v0, v1), h23 = packh2(v2, v3);
                *(uint32_t*)(Chi + (size_t)m0*GN + n)     = h01;
                *(uint32_t*)(Chi + (size_t)(m0+8)*GN + n) = h23;
                if (OMODE == 1) {
                    float2 f01 = unpackh2(h01), f23 = unpackh2(h23);
                    *(uint32_t*)(Clo + (size_t)m0*GN + n) =
                        packh2(v0 - f01.x, v1 - f01.y);
                    *(uint32_t*)(Clo + (size_t)(m0+8)*GN + n) =
                        packh2(v2 - f23.x, v3 - f23.y);
                }
            }
        }
    }
}

#define SMEM_2P (2*(2*AT_B + BT_B))   /* 73728 -> 3 CTAs/SM */
#define SMEM_1P (2*(AT_B + BT_B))     /* 55296 -> 4 CTAs/SM */

// Q projection: 2-pass input, hi-only output (flash no longer needs Ql)
__global__ __launch_bounds__(256, 3)
void gemm_q(const __half* __restrict__ Xh, const __half* __restrict__ Xl,
            const __half* __restrict__ Wqh, __half* __restrict__ Qh)
{
    extern __shared__ char smem[];
    gemm64_core<2, 2>(Xh, Xl, Wqh, nullptr, Qh, nullptr, 0.125f,
                      blockIdx.y << 6, blockIdx.x << 7, smem);
}

// K/V projections: 1-pass input, hi-only output, 4 CTAs/SM
__global__ __launch_bounds__(256, 4)
void gemm_kv(const __half* __restrict__ Xh,
             const __half* __restrict__ Wkh, const __half* __restrict__ Wvh,
             __half* __restrict__ Kh, __half* __restrict__ Vh)
{
    extern __shared__ char smem[];
    const __half* Bh = blockIdx.z ? Wvh : Wkh;
    __half* Chi      = blockIdx.z ? Vh  : Kh;
    gemm64_core<1, 2>(Xh, nullptr, Bh, nullptr, Chi, nullptr, 1.0f,
                      blockIdx.y << 6, blockIdx.x << 7, smem);
}

__global__ __launch_bounds__(256, 3)
void gemm_out(const __half* __restrict__ AOh, const __half* __restrict__ AOl,
              const __half* __restrict__ Woh, float* __restrict__ out)
{
    extern __shared__ char smem[];
    gemm64_core<2, 0>(AOh, AOl, Woh, out, nullptr, nullptr, 1.0f,
                      blockIdx.y << 6, blockIdx.x << 7, smem);
}

// ---------------------------------------------------------------------------
// Flash attention, causal: S = Qh*Kh (1 pass), O = (Ph+Pl)*Vh (2 passes).
// 64-row q-tiles, 128 threads, 3-stage KV, 3 CTAs/SM.
// ---------------------------------------------------------------------------
#define FQSTR 72
#define FTILE (64*FQSTR*2)
#define FSTAGE (2*FTILE)
#define FLASH_SMEM (FTILE + 3*FSTAGE)    /* 64512 */

__global__ __launch_bounds__(128, 3)
void flash_mma(const __half* __restrict__ Qh_,
               const __half* __restrict__ Kh_, const __half* __restrict__ Vh_,
               __half* __restrict__ AOh, __half* __restrict__ AOl)
{
    extern __shared__ char smc[];
    const int qt  = (int)gridDim.x - 1 - (int)blockIdx.x;
    const int h   = blockIdx.y, b = blockIdx.z;
    const int tid = threadIdx.x;
    const int lane = tid & 31, w = tid >> 5;
    const int qbase = qt*64;
    const int ktmax = qt;

    const uint32_t sb  = smem_u32(smc);
    const uint32_t uQh = sb;
    const uint32_t uKV = sb + FTILE;

    const __half* kvsrc[2] = {Kh_, Vh_};
    const size_t hofs = (size_t)h*64;

    auto load_kv = [&](int kt, int s) {
#pragma unroll
        for (int i = 0; i < 8; i++) {
            int id = tid + i*128;
            int a = id >> 9, r = (id >> 3) & 63, c = id & 7;
            const __half* g = kvsrc[a] + (size_t)(b*SS + kt*64 + r)*DD + hofs + c*8;
            cp_async16(uKV + s*FSTAGE + a*FTILE + (uint32_t)(r*FQSTR + c*8)*2, g);
        }
    };

#pragma unroll
    for (int i = 0; i < 4; i++) {
        int id = tid + i*128;
        int r = id >> 3, c = id & 7;
        const __half* g = Qh_ + (size_t)(b*SS + qbase + r)*DD + hofs + c*8;
        cp_async16(uQh + (uint32_t)(r*FQSTR + c*8)*2, g);
    }
    load_kv(0, 0);
    cp_commit();
    if (ktmax >= 1) { load_kv(1, 1); cp_commit(); }

    const int gid = lane >> 2, tig = lane & 3;
    const int qrow_off = ((lane>>3)&1)*8 + (lane&7);
    const int qd_off   = (lane>>4)*8;
    const int krow_off = (lane>>4)*8 + (lane&7);
    const int kd_off   = ((lane>>3)&1)*8;
    const int vrow_off = ((lane>>3)&1)*8 + (lane&7);
    const int vd_off   = (lane>>4)*8;

    uint32_t qh[4][4];

    float m0 = -INFINITY, m1 = -INFINITY, l0 = 0.f, l1 = 0.f;
    float oacc[8][4];
#pragma unroll
    for (int nt = 0; nt < 8; nt++)
#pragma unroll
        for (int q = 0; q < 4; q++) oacc[nt][q] = 0.f;

    const int row0 = qbase + 16*w + gid;
    const int row1 = row0 + 8;

    for (int kt = 0; kt <= ktmax; kt++) {
        if (kt + 2 <= ktmax) { load_kv(kt + 2, (kt + 2) % 3); cp_commit(); }
        if (kt + 2 <= ktmax)      cp_wait<2>();
        else if (kt + 1 <= ktmax) cp_wait<1>();
        else                      cp_wait<0>();
        __syncthreads();

        if (kt == 0) {
            uint32_t ah = uQh + (uint32_t)((16*w + qrow_off)*FQSTR + qd_off)*2;
#pragma unroll
            for (int kk = 0; kk < 4; kk++)
                ldm_x4(qh[kk], ah + kk*32);
        }

        const uint32_t st = uKV + (uint32_t)(kt % 3)*FSTAGE;
        {
            float sacc[8][4];
#pragma unroll
            for (int nt = 0; nt < 8; nt++)
#pragma unroll
                for (int q = 0; q < 4; q++) sacc[nt][q] = 0.f;

            // ---- S = Qh * Kh ----
#pragma unroll
            for (int kk = 0; kk < 4; kk++) {
                const uint32_t kb0 = st + (uint32_t)(krow_off*FQSTR + kd_off + 16*kk)*2;
                uint32_t kb[8][2];
#pragma unroll
                for (int p = 0; p < 4; p++) {
                    uint32_t r[4];
                    ldm_x4(r, kb0 + (uint32_t)(16*p*FQSTR)*2);
                    kb[2*p][0] = r[0]; kb[2*p][1] = r[1];
                    kb[2*p+1][0] = r[2]; kb[2*p+1][1] = r[3];
                }
#pragma unroll
                for (int nt = 0; nt < 8; nt++)
                    mma_f32acc(sacc[nt], qh[kk], kb[nt]);
            }

            if (kt == qt) {
                const int colb = kt*64 + 2*tig;
#pragma unroll
                for (int nt = 0; nt < 8; nt++) {
                    int c0 = colb + 8*nt, c1 = c0 + 1;
                    if (c0 > row0) sacc[nt][0] = -1e10f;
                    if (c1 > row0) sacc[nt][1] = -1e10f;
                    if (c0 > row1) sacc[nt][2] = -1e10f;
                    if (c1 > row1) sacc[nt][3] = -1e10f;
                }
            }

            float rm0 = -INFINITY, rm1 = -INFINITY;
#pragma unroll
            for (int nt = 0; nt < 8; nt++) {
                rm0 = fmaxf(rm0, fmaxf(sacc[nt][0], sacc[nt][1]));
                rm1 = fmaxf(rm1, fmaxf(sacc[nt][2], sacc[nt][3]));
            }
            rm0 = warp_rmax(rm0); rm1 = warp_rmax(rm1);
            float mn0 = fmaxf(m0, rm0), mn1 = fmaxf(m1, rm1);
            float cr0 = __expf(m0 - mn0), cr1 = __expf(m1 - mn1);
            m0 = mn0; m1 = mn1;
            float ps0 = 0.f, ps1 = 0.f;
#pragma unroll
            for (int nt = 0; nt < 8; nt++) {
                float p0 = __expf(sacc[nt][0] - mn0);
                float p1 = __expf(sacc[nt][1] - mn0);
                float p2 = __expf(sacc[nt][2] - mn1);
                float p3 = __expf(sacc[nt][3] - mn1);
                sacc[nt][0] = p0; sacc[nt][1] = p1; sacc[nt][2] = p2; sacc[nt][3] = p3;
                ps0 += p0 + p1; ps1 += p2 + p3;
            }
            ps0 = warp_rsum(ps0); ps1 = warp_rsum(ps1);
            l0 = l0*cr0 + ps0; l1 = l1*cr1 + ps1;
#pragma unroll
            for (int nt = 0; nt < 8; nt++) {
                oacc[nt][0] *= cr0; oacc[nt][1] *= cr0;
                oacc[nt][2] *= cr1; oacc[nt][3] *= cr1;
            }

            // ---- O += (Ph + Pl) * Vh ----
#pragma unroll
            for (int kk = 0; kk < 4; kk++) {
                uint32_t pah[4], pal[4];
#pragma unroll
                for (int jj = 0; jj < 2; jj++) {
                    const float* s4 = sacc[2*kk + jj];
                    uint32_t h01 = packh2(s4[0], s4[1]);
                    uint32_t h23 = packh2(s4[2], s4[3]);
                    float2 f01 = unpackh2(h01), f23 = unpackh2(h23);
                    pah[2*jj]   = h01;
                    pah[2*jj+1] = h23;
                    pal[2*jj]   = packh2(s4[0] - f01.x, s4[1] - f01.y);
                    pal[2*jj+1] = packh2(s4[2] - f23.x, s4[3] - f23.y);
                }
                const uint32_t vb0 = st + FTILE + (uint32_t)((16*kk + vrow_off)*FQSTR + vd_off)*2;
                uint32_t vb[8][2];
#pragma unroll
                for (int p = 0; p < 4; p++) {
                    uint32_t r[4];
                    ldm_x4_t(r, vb0 + (uint32_t)(16*p)*2);
                    vb[2*p][0] = r[0]; vb[2*p][1] = r[1];
                    vb[2*p+1][0] = r[2]; vb[2*p+1][1] = r[3];
                }
#pragma unroll
                for (int nt = 0; nt < 8; nt++) {
                    mma_f32acc(oacc[nt], pah, vb[nt]);
                    mma_f32acc(oacc[nt], pal, vb[nt]);
                }
            }
        }
        __syncthreads();
    }

    const float inv0 = 1.f / l0, inv1 = 1.f / l1;
    const size_t r0g = (size_t)(b*SS + row0);
    const size_t r1g = (size_t)(b*SS + row1);
#pragma unroll
    for (int nt = 0; nt < 8; nt++) {
        const size_t col = hofs + 8*nt + 2*tig;
        float x0 = oacc[nt][0]*inv0, x1 = oacc[nt][1]*inv0;
        float x2 = oacc[nt][2]*inv1, x3 = oacc[nt][3]*inv1;
        uint32_t h01 = packh2(x0, x1), h23 = packh2(x2, x3);
        float2 f01 = unpackh2(h01), f23 = unpackh2(h23);
        uint32_t l01 = packh2(x0 - f01.x, x1 - f01.y);
        uint32_t l23 = packh2(x2 - f23.x, x3 - f23.y);
        *(uint32_t*)(AOh + r0g*DD + col) = h01;
        *(uint32_t*)(AOl + r0g*DD + col) = l01;
        *(uint32_t*)(AOh + r1g*DD + col) = h23;
        *(uint32_t*)(AOl + r1g*DD + col) = l23;
    }
}

// ---------------------------------------------------------------------------
extern "C" void kernel_launch(void* const* d_in, const int* in_sizes, int n_in,
                              void* d_out, int out_size)
{
    (void)in_sizes; (void)n_in; (void)out_size;
    const float* X  = (const float*)d_in[0];
    const float* Wq = (const float*)d_in[1];
    const float* Wk = (const float*)d_in[2];
    const float* Wv = (const float*)d_in[3];
    const float* Wo = (const float*)d_in[4];
    float* out = (float*)d_out;

    __half *Xh, *Xl, *Qh, *Kh, *Vh, *AOh, *AOl;
    __half *Wqh, *Wkh, *Wvh, *Woh;
    cudaGetSymbolAddress((void**)&Xh,  g_Xh);
    cudaGetSymbolAddress((void**)&Xl,  g_Xl);
    cudaGetSymbolAddress((void**)&Qh,  g_Qh);
    cudaGetSymbolAddress((void**)&Kh,  g_Kh);
    cudaGetSymbolAddress((void**)&Vh,  g_Vh);
    cudaGetSymbolAddress((void**)&AOh, g_AOh);
    cudaGetSymbolAddress((void**)&AOl, g_AOl);
    cudaGetSymbolAddress((void**)&Wqh, g_Wqh);
    cudaGetSymbolAddress((void**)&Wkh, g_Wkh);
    cudaGetSymbolAddress((void**)&Wvh, g_Wvh);
    cudaGetSymbolAddress((void**)&Woh, g_Woh);

    cudaFuncSetAttribute(gemm_q,   cudaFuncAttributeMaxDynamicSharedMemorySize, SMEM_2P);
    cudaFuncSetAttribute(gemm_kv,  cudaFuncAttributeMaxDynamicSharedMemorySize, SMEM_1P);
    cudaFuncSetAttribute(gemm_out, cudaFuncAttributeMaxDynamicSharedMemorySize, SMEM_2P);
    cudaFuncSetAttribute(flash_mma, cudaFuncAttributeMaxDynamicSharedMemorySize, FLASH_SMEM);

    convert_all<<<2048, 256>>>(X, Wq, Wk, Wv, Wo, Xh, Xl, Wqh, Wkh, Wvh, Woh);

    gemm_q <<<dim3(GN/128, GM/64, 1), 256, SMEM_2P>>>(Xh, Xl, Wqh, Qh);
    gemm_kv<<<dim3(GN/128, GM/64, 2), 256, SMEM_1P>>>(Xh, Wkh, Wvh, Kh, Vh);

    flash_mma<<<dim3(SS/64, HH, BB), 128, FLASH_SMEM>>>(Qh, Kh, Vh, AOh, AOl);

    gemm_out<<<dim3(GN/128, GM/64, 1), 256, SMEM_2P>>>(AOh, AOl, Woh, out);
}